// round 1
// baseline (speedup 1.0000x reference)
#include <cuda_runtime.h>

#define CC 4
#define LL 1024
#define HH 8
#define DD 64
#define TT (CC*LL)
#define QSCALE 0.125f
#define EPSV 1e-6f

// Scratch (static __device__ — no allocation allowed)
__device__ float g_buf[CC*HH*LL];                       // [c][h][l] cumsum of log_g
__device__ float P_buf[(size_t)CC*HH*DD*DD*DD];         // [c][h][d][e][v]; after scan: S_prev
__device__ float Z_buf[CC*HH*DD*DD];                    // [c][h][d][e]; after scan: sk_prev
__device__ float row_buf[TT*HH];                        // intra row sums

// ---------------------------------------------------------------------------
// K0: per-(c,h) inclusive cumsum of log_g over the chunk (L=1024), 256 threads
// ---------------------------------------------------------------------------
__global__ void cumsum_kernel(const float* __restrict__ lg) {
    int c = blockIdx.x / HH, h = blockIdx.x % HH;
    int t = threadIdx.x;
    float vloc[4];
    float s = 0.f;
#pragma unroll
    for (int i = 0; i < 4; i++) {
        int l = t * 4 + i;
        s += lg[(c * LL + l) * HH + h];
        vloc[i] = s;
    }
    float tot = s;
#pragma unroll
    for (int off = 1; off < 32; off <<= 1) {
        float n = __shfl_up_sync(0xffffffffu, tot, off);
        if ((t & 31) >= off) tot += n;
    }
    __shared__ float wsum[8];
    __shared__ float woff[8];
    if ((t & 31) == 31) wsum[t >> 5] = tot;
    __syncthreads();
    if (t == 0) {
        float a = 0.f;
        for (int w = 0; w < 8; w++) { woff[w] = a; a += wsum[w]; }
    }
    __syncthreads();
    float ex = woff[t >> 5] + (tot - s);   // exclusive prefix for this thread
#pragma unroll
    for (int i = 0; i < 4; i++)
        g_buf[(c * HH + h) * LL + t * 4 + i] = ex + vloc[i];
}

// float4-group XOR swizzle for transposed [d][r] tiles (conflict-reduced STS,
// conflict-free LDS.128 in the k-loop)
__device__ __forceinline__ int swoff(int d, int r) {
    return d * 64 + ((((r >> 2) ^ (d & 15)) << 2) | (r & 3));
}

// ---------------------------------------------------------------------------
// K1: intra-chunk causal attention. grid (16, H, C), 256 threads.
// Block computes 64 rows x 64 outputs. Smem = exactly 48KB.
// ---------------------------------------------------------------------------
__global__ void __launch_bounds__(256, 1) intra_kernel(
    const float* __restrict__ q, const float* __restrict__ k,
    const float* __restrict__ v, float* __restrict__ out) {
    const int tile = blockIdx.x, h = blockIdx.y, c = blockIdx.z;
    const int tid = threadIdx.x, ty = tid >> 4, tx = tid & 15;
    __shared__ __align__(16) float Qt[4096];  // q transposed+swizzled, scaled
    __shared__ __align__(16) float KW[4096];  // union: K transposed+swizzled / W staging
    __shared__ __align__(16) float Vs[4096];  // V [s][v]
    const int l0 = tile * 64;
    const size_t qkbase = ((size_t)(c * LL + l0) * HH + h) * DD;

    for (int i = tid; i < 1024; i += 256) {
        int l = i >> 4, d4 = (i & 15) << 2;
        const float4 qv = *(const float4*)&q[qkbase + (size_t)l * HH * DD + d4];
        Qt[swoff(d4 + 0, l)] = qv.x * QSCALE;
        Qt[swoff(d4 + 1, l)] = qv.y * QSCALE;
        Qt[swoff(d4 + 2, l)] = qv.z * QSCALE;
        Qt[swoff(d4 + 3, l)] = qv.w * QSCALE;
    }
    float gqr[4];
#pragma unroll
    for (int i = 0; i < 4; i++) gqr[i] = g_buf[(c * HH + h) * LL + l0 + ty * 4 + i];

    float acc[4][4], rowacc[4];
#pragma unroll
    for (int i = 0; i < 4; i++) {
        rowacc[i] = 0.f;
#pragma unroll
        for (int j = 0; j < 4; j++) acc[i][j] = 0.f;
    }

    for (int st = 0; st <= tile; st++) {
        const int s0 = st * 64;
        const size_t kbase = ((size_t)(c * LL + s0) * HH + h) * DD;
        __syncthreads();  // prev GEMM2 done with KW/Vs
        for (int i = tid; i < 1024; i += 256) {
            int s = i >> 4, d4 = (i & 15) << 2;
            const float4 kv = *(const float4*)&k[kbase + (size_t)s * HH * DD + d4];
            KW[swoff(d4 + 0, s)] = kv.x;
            KW[swoff(d4 + 1, s)] = kv.y;
            KW[swoff(d4 + 2, s)] = kv.z;
            KW[swoff(d4 + 3, s)] = kv.w;
            *(float4*)&Vs[s * 64 + d4] =
                *(const float4*)&v[kbase + (size_t)s * HH * DD + d4];
        }
        float gkr[4];
#pragma unroll
        for (int j = 0; j < 4; j++)
            gkr[j] = g_buf[(c * HH + h) * LL + s0 + tx * 4 + j];
        __syncthreads();

        // GEMM1: scores = Qs * K^T (reduce over d)
        float sc[4][4];
#pragma unroll
        for (int i = 0; i < 4; i++)
#pragma unroll
            for (int j = 0; j < 4; j++) sc[i][j] = 0.f;
#pragma unroll 8
        for (int d = 0; d < 64; d++) {
            const float4 av = *(const float4*)&Qt[d * 64 + ((ty ^ (d & 15)) << 2)];
            const float4 bv = *(const float4*)&KW[d * 64 + ((tx ^ (d & 15)) << 2)];
            const float a[4] = {av.x, av.y, av.z, av.w};
            const float b[4] = {bv.x, bv.y, bv.z, bv.w};
#pragma unroll
            for (int i = 0; i < 4; i++)
#pragma unroll
                for (int j = 0; j < 4; j++) sc[i][j] += a[i] * b[j];
        }
        __syncthreads();  // done reading K before overwriting with W

        const bool diag = (st == tile);
#pragma unroll
        for (int i = 0; i < 4; i++) {
            float w[4];
#pragma unroll
            for (int j = 0; j < 4; j++) {
                float e = __expf(gqr[i] - gkr[j]);
                float scv = sc[i][j];
                float wv = e * scv * scv;
                if (diag && (ty * 4 + i) < (tx * 4 + j)) wv = 0.f;
                w[j] = wv;
            }
            ((float4*)&KW[(ty * 4 + i) * 64])[tx] = make_float4(w[0], w[1], w[2], w[3]);
        }
        __syncthreads();  // W visible

        // GEMM2: O += W * V (reduce over s), row += sum_s W
#pragma unroll 8
        for (int s = 0; s < 64; s++) {
            float a[4];
#pragma unroll
            for (int i = 0; i < 4; i++) a[i] = KW[(ty * 4 + i) * 64 + s];
            const float4 bv = *(const float4*)&Vs[s * 64 + tx * 4];
#pragma unroll
            for (int i = 0; i < 4; i++) {
                acc[i][0] += a[i] * bv.x;
                acc[i][1] += a[i] * bv.y;
                acc[i][2] += a[i] * bv.z;
                acc[i][3] += a[i] * bv.w;
            }
            if (tx == 0) {
#pragma unroll
                for (int i = 0; i < 4; i++) rowacc[i] += a[i];
            }
        }
    }

#pragma unroll
    for (int i = 0; i < 4; i++) {
        const int t_ = c * LL + l0 + ty * 4 + i;
        *(float4*)&out[((size_t)t_ * HH + h) * DD + tx * 4] =
            make_float4(acc[i][0], acc[i][1], acc[i][2], acc[i][3]);
        if (tx == 0) row_buf[t_ * HH + h] = rowacc[i];
    }
}

// ---------------------------------------------------------------------------
// K2a: per-chunk expanded state P[d,e,v] and normalizer Z[d,e].
// grid (D, H, C), 256 threads; each block: one d -> 64x64x1024 GEMM.
// ---------------------------------------------------------------------------
__global__ void __launch_bounds__(256, 1) pz_kernel(
    const float* __restrict__ k, const float* __restrict__ v) {
    const int d = blockIdx.x, h = blockIdx.y, c = blockIdx.z;
    const int tid = threadIdx.x, ty = tid >> 4, tx = tid & 15;
    __shared__ __align__(16) float Ks[4096];
    __shared__ __align__(16) float Vs[4096];
    __shared__ float wl[64];
    const float gend = g_buf[(c * HH + h) * LL + LL - 1];

    float acc[4][4], zacc[4];
#pragma unroll
    for (int i = 0; i < 4; i++) {
        zacc[i] = 0.f;
#pragma unroll
        for (int j = 0; j < 4; j++) acc[i][j] = 0.f;
    }

    for (int lt = 0; lt < 16; lt++) {
        const int lb = lt * 64;
        const size_t kbase = ((size_t)(c * LL + lb) * HH + h) * DD;
        __syncthreads();
        for (int i = tid; i < 1024; i += 256) {
            int l = i >> 4, e4 = (i & 15) << 2;
            *(float4*)&Ks[l * 64 + e4] =
                *(const float4*)&k[kbase + (size_t)l * HH * DD + e4];
            *(float4*)&Vs[l * 64 + e4] =
                *(const float4*)&v[kbase + (size_t)l * HH * DD + e4];
        }
        if (tid < 64) {
            int l = lb + tid;
            wl[tid] = k[((size_t)(c * LL + l) * HH + h) * DD + d] *
                      __expf(gend - g_buf[(c * HH + h) * LL + l]);
        }
        __syncthreads();
#pragma unroll 8
        for (int l = 0; l < 64; l++) {
            const float w = wl[l];
            const float4 av = ((const float4*)&Ks[l * 64])[ty];
            const float4 bv = ((const float4*)&Vs[l * 64])[tx];
            const float a[4] = {w * av.x, w * av.y, w * av.z, w * av.w};
#pragma unroll
            for (int i = 0; i < 4; i++) {
                acc[i][0] += a[i] * bv.x;
                acc[i][1] += a[i] * bv.y;
                acc[i][2] += a[i] * bv.z;
                acc[i][3] += a[i] * bv.w;
            }
            if (tx == 0) {
#pragma unroll
                for (int i = 0; i < 4; i++) zacc[i] += a[i];
            }
        }
    }

    float* Pp = &P_buf[(((size_t)(c * HH + h) * DD + d) << 12)];
#pragma unroll
    for (int i = 0; i < 4; i++)
        *(float4*)&Pp[(ty * 4 + i) * 64 + tx * 4] =
            make_float4(acc[i][0], acc[i][1], acc[i][2], acc[i][3]);
    if (tx == 0) {
#pragma unroll
        for (int i = 0; i < 4; i++)
            Z_buf[((c * HH + h) * DD + d) * DD + ty * 4 + i] = zacc[i];
    }
}

// ---------------------------------------------------------------------------
// K2b: in-place scan over chunks. buf[c][h][r] -> prefix state before chunk c.
// which=0 -> P_buf (per=D^3), which=1 -> Z_buf (per=D^2)
// ---------------------------------------------------------------------------
__global__ void scan_kernel(int which, int per) {
    int gid = blockIdx.x * blockDim.x + threadIdx.x;
    if (gid >= HH * per) return;
    int h = gid / per, r = gid % per;
    float* buf = which ? Z_buf : P_buf;
    float s = 0.f;
#pragma unroll
    for (int c = 0; c < CC; c++) {
        float gt = __expf(g_buf[(c * HH + h) * LL + LL - 1]);
        size_t off = (size_t)(c * HH + h) * per + r;
        float p = buf[off];
        buf[off] = s;
        s = gt * s + p;
    }
}

// ---------------------------------------------------------------------------
// K3: inter-chunk contribution via state + finalize (divide).
// grid (16, H, C), 256 threads; streams S row-by-row with register prefetch.
// ---------------------------------------------------------------------------
__global__ void __launch_bounds__(256, 1) inter_kernel(
    const float* __restrict__ q, float* __restrict__ out) {
    const int tile = blockIdx.x, h = blockIdx.y, c = blockIdx.z;
    const int tid = threadIdx.x, ty = tid >> 4, tx = tid & 15;
    __shared__ __align__(16) float Qs[4096];   // [l][d], scaled
    __shared__ __align__(16) float Ss[4096];   // S_prev row d: [e][v]
    __shared__ float sks[64];
    __shared__ float denl[64];
    __shared__ float gq[64];
    const int l0 = tile * 64;
    const size_t qbase = ((size_t)(c * LL + l0) * HH + h) * DD;

    for (int i = tid; i < 1024; i += 256) {
        int l = i >> 4, d4 = (i & 15) << 2;
        float4 qv = *(const float4*)&q[qbase + (size_t)l * HH * DD + d4];
        qv.x *= QSCALE; qv.y *= QSCALE; qv.z *= QSCALE; qv.w *= QSCALE;
        *(float4*)&Qs[l * 64 + d4] = qv;
    }
    if (tid < 64) gq[tid] = g_buf[(c * HH + h) * LL + l0 + tid];

    const float* Sp = &P_buf[(size_t)(c * HH + h) * DD * DD * DD];
    const float* zp = &Z_buf[(size_t)(c * HH + h) * DD * DD];
    for (int i = tid; i < 4096; i += 256) Ss[i] = Sp[i];
    if (tid < 64) sks[tid] = zp[tid];
    __syncthreads();

    float acc[4][4], dacc[4];
#pragma unroll
    for (int i = 0; i < 4; i++) {
        dacc[i] = 0.f;
#pragma unroll
        for (int j = 0; j < 4; j++) acc[i][j] = 0.f;
    }

    for (int d = 0; d < 64; d++) {
        float rg[16];
        float rz = 0.f;
        if (d < 63) {
            const float* np = Sp + (size_t)(d + 1) * 4096;
#pragma unroll
            for (int u = 0; u < 16; u++) rg[u] = np[tid + u * 256];
            if (tid < 64) rz = zp[(d + 1) * 64 + tid];
        }
        float qd[4];
#pragma unroll
        for (int i = 0; i < 4; i++) qd[i] = Qs[(ty * 4 + i) * 64 + d];
#pragma unroll 8
        for (int e = 0; e < 64; e++) {
            const float4 bv = *(const float4*)&Ss[e * 64 + tx * 4];
            const float ske = sks[e];
            float a[4];
#pragma unroll
            for (int i = 0; i < 4; i++) a[i] = qd[i] * Qs[(ty * 4 + i) * 64 + e];
#pragma unroll
            for (int i = 0; i < 4; i++) {
                acc[i][0] += a[i] * bv.x;
                acc[i][1] += a[i] * bv.y;
                acc[i][2] += a[i] * bv.z;
                acc[i][3] += a[i] * bv.w;
            }
            if (tx == 0) {
#pragma unroll
                for (int i = 0; i < 4; i++) dacc[i] += a[i] * ske;
            }
        }
        __syncthreads();  // all done reading Ss/sks
        if (d < 63) {
#pragma unroll
            for (int u = 0; u < 16; u++) Ss[tid + u * 256] = rg[u];
            if (tid < 64) sks[tid] = rz;
        }
        __syncthreads();  // new row visible
    }

    if (tx == 0) {
#pragma unroll
        for (int i = 0; i < 4; i++) denl[ty * 4 + i] = dacc[i];
    }
    __syncthreads();

#pragma unroll
    for (int i = 0; i < 4; i++) {
        const int li = ty * 4 + i;
        const int t_ = c * LL + l0 + li;
        const float qdec = __expf(gq[li]);
        float den = row_buf[t_ * HH + h] + qdec * denl[li];
        den = fmaxf(den, EPSV);
        const float inv = 1.f / den;
        const size_t o = ((size_t)t_ * HH + h) * DD + tx * 4;
        float4 ov = *(float4*)&out[o];
        ov.x = (ov.x + qdec * acc[i][0]) * inv;
        ov.y = (ov.y + qdec * acc[i][1]) * inv;
        ov.z = (ov.z + qdec * acc[i][2]) * inv;
        ov.w = (ov.w + qdec * acc[i][3]) * inv;
        *(float4*)&out[o] = ov;
    }
}

extern "C" void kernel_launch(void* const* d_in, const int* in_sizes, int n_in,
                              void* d_out, int out_size) {
    const float* q = (const float*)d_in[0];
    const float* k = (const float*)d_in[1];
    const float* v = (const float*)d_in[2];
    const float* lg = (const float*)d_in[3];
    float* out = (float*)d_out;

    cumsum_kernel<<<CC * HH, 256>>>(lg);

    dim3 gt(16, HH, CC);
    intra_kernel<<<gt, 256>>>(q, k, v, out);

    dim3 gp(DD, HH, CC);
    pz_kernel<<<gp, 256>>>(k, v);

    scan_kernel<<<(HH * DD * DD * DD + 255) / 256, 256>>>(0, DD * DD * DD);
    scan_kernel<<<(HH * DD * DD + 255) / 256, 256>>>(1, DD * DD);

    inter_kernel<<<gt, 256>>>(q, out);
}

// round 2
// speedup vs baseline: 1.8702x; 1.8702x over previous
#include <cuda_runtime.h>

#define CC 4
#define LL 1024
#define HH 8
#define DD 64
#define TT (CC*LL)
#define QSCALE 0.125f
#define EPSV 1e-6f
#define PTOT 2112   // 2080 unique (d<=e) pairs + 32 pad
#define PREAL 2080

// Scratch (static __device__ — no allocation allowed)
__device__ float g_buf[CC*HH*LL];                 // [c][h][l] cumsum of log_g
__device__ float P_buf[(size_t)3*HH*PTOT*DD];     // [c'][h][p][v], c'=0..2 only
__device__ float z_buf[3*HH*PTOT];                // [c'][h][p]
__device__ float row_buf[TT*HH];                  // intra row sums
__device__ int   lut_d[PTOT];
__device__ int   lut_e[PTOT];
__device__ float lut_m[PTOT];                     // 1 (d==e), 2 (d<e), 0 (pad)

// ---------------------------------------------------------------------------
// K0: cumsum per (c,h) + pair-LUT build (last block)
// ---------------------------------------------------------------------------
__global__ void init_kernel(const float* __restrict__ lg) {
    if (blockIdx.x == CC * HH) {
        // build triangular pair LUT
        for (int p = threadIdx.x; p < PTOT; p += 256) {
            int d = 0, e = 0; float m = 0.f;
            if (p < PREAL) {
                int off = 0;
                while (off + (DD - d) <= p) { off += DD - d; d++; }
                e = d + (p - off);
                m = (d == e) ? 1.f : 2.f;
            }
            lut_d[p] = d; lut_e[p] = e; lut_m[p] = m;
        }
        return;
    }
    int c = blockIdx.x / HH, h = blockIdx.x % HH;
    int t = threadIdx.x;
    float vloc[4];
    float s = 0.f;
#pragma unroll
    for (int i = 0; i < 4; i++) {
        int l = t * 4 + i;
        s += lg[(c * LL + l) * HH + h];
        vloc[i] = s;
    }
    float tot = s;
#pragma unroll
    for (int off = 1; off < 32; off <<= 1) {
        float n = __shfl_up_sync(0xffffffffu, tot, off);
        if ((t & 31) >= off) tot += n;
    }
    __shared__ float wsum[8];
    __shared__ float woff[8];
    if ((t & 31) == 31) wsum[t >> 5] = tot;
    __syncthreads();
    if (t == 0) {
        float a = 0.f;
        for (int w = 0; w < 8; w++) { woff[w] = a; a += wsum[w]; }
    }
    __syncthreads();
    float ex = woff[t >> 5] + (tot - s);
#pragma unroll
    for (int i = 0; i < 4; i++)
        g_buf[(c * HH + h) * LL + t * 4 + i] = ex + vloc[i];
}

// float4-group XOR swizzle (used by intra only)
__device__ __forceinline__ int swoff(int d, int r) {
    return d * 64 + ((((r >> 2) ^ (d & 15)) << 2) | (r & 3));
}

// ---------------------------------------------------------------------------
// K1: intra-chunk causal attention (unchanged from R1). grid (16, H, C), 256t.
// ---------------------------------------------------------------------------
__global__ void __launch_bounds__(256, 1) intra_kernel(
    const float* __restrict__ q, const float* __restrict__ k,
    const float* __restrict__ v, float* __restrict__ out) {
    const int tile = blockIdx.x, h = blockIdx.y, c = blockIdx.z;
    const int tid = threadIdx.x, ty = tid >> 4, tx = tid & 15;
    __shared__ __align__(16) float Qt[4096];
    __shared__ __align__(16) float KW[4096];
    __shared__ __align__(16) float Vs[4096];
    const int l0 = tile * 64;
    const size_t qkbase = ((size_t)(c * LL + l0) * HH + h) * DD;

    for (int i = tid; i < 1024; i += 256) {
        int l = i >> 4, d4 = (i & 15) << 2;
        const float4 qv = *(const float4*)&q[qkbase + (size_t)l * HH * DD + d4];
        Qt[swoff(d4 + 0, l)] = qv.x * QSCALE;
        Qt[swoff(d4 + 1, l)] = qv.y * QSCALE;
        Qt[swoff(d4 + 2, l)] = qv.z * QSCALE;
        Qt[swoff(d4 + 3, l)] = qv.w * QSCALE;
    }
    float gqr[4];
#pragma unroll
    for (int i = 0; i < 4; i++) gqr[i] = g_buf[(c * HH + h) * LL + l0 + ty * 4 + i];

    float acc[4][4], rowacc[4];
#pragma unroll
    for (int i = 0; i < 4; i++) {
        rowacc[i] = 0.f;
#pragma unroll
        for (int j = 0; j < 4; j++) acc[i][j] = 0.f;
    }

    for (int st = 0; st <= tile; st++) {
        const int s0 = st * 64;
        const size_t kbase = ((size_t)(c * LL + s0) * HH + h) * DD;
        __syncthreads();
        for (int i = tid; i < 1024; i += 256) {
            int s = i >> 4, d4 = (i & 15) << 2;
            const float4 kv = *(const float4*)&k[kbase + (size_t)s * HH * DD + d4];
            KW[swoff(d4 + 0, s)] = kv.x;
            KW[swoff(d4 + 1, s)] = kv.y;
            KW[swoff(d4 + 2, s)] = kv.z;
            KW[swoff(d4 + 3, s)] = kv.w;
            *(float4*)&Vs[s * 64 + d4] =
                *(const float4*)&v[kbase + (size_t)s * HH * DD + d4];
        }
        float gkr[4];
#pragma unroll
        for (int j = 0; j < 4; j++)
            gkr[j] = g_buf[(c * HH + h) * LL + s0 + tx * 4 + j];
        __syncthreads();

        float sc[4][4];
#pragma unroll
        for (int i = 0; i < 4; i++)
#pragma unroll
            for (int j = 0; j < 4; j++) sc[i][j] = 0.f;
#pragma unroll 8
        for (int d = 0; d < 64; d++) {
            const float4 av = *(const float4*)&Qt[d * 64 + ((ty ^ (d & 15)) << 2)];
            const float4 bv = *(const float4*)&KW[d * 64 + ((tx ^ (d & 15)) << 2)];
            const float a[4] = {av.x, av.y, av.z, av.w};
            const float b[4] = {bv.x, bv.y, bv.z, bv.w};
#pragma unroll
            for (int i = 0; i < 4; i++)
#pragma unroll
                for (int j = 0; j < 4; j++) sc[i][j] += a[i] * b[j];
        }
        __syncthreads();

        const bool diag = (st == tile);
#pragma unroll
        for (int i = 0; i < 4; i++) {
            float w[4];
#pragma unroll
            for (int j = 0; j < 4; j++) {
                float e = __expf(gqr[i] - gkr[j]);
                float scv = sc[i][j];
                float wv = e * scv * scv;
                if (diag && (ty * 4 + i) < (tx * 4 + j)) wv = 0.f;
                w[j] = wv;
            }
            ((float4*)&KW[(ty * 4 + i) * 64])[tx] = make_float4(w[0], w[1], w[2], w[3]);
        }
        __syncthreads();

#pragma unroll 8
        for (int s = 0; s < 64; s++) {
            float a[4];
#pragma unroll
            for (int i = 0; i < 4; i++) a[i] = KW[(ty * 4 + i) * 64 + s];
            const float4 bv = *(const float4*)&Vs[s * 64 + tx * 4];
#pragma unroll
            for (int i = 0; i < 4; i++) {
                acc[i][0] += a[i] * bv.x;
                acc[i][1] += a[i] * bv.y;
                acc[i][2] += a[i] * bv.z;
                acc[i][3] += a[i] * bv.w;
            }
            if (tx == 0) {
#pragma unroll
                for (int i = 0; i < 4; i++) rowacc[i] += a[i];
            }
        }
    }

#pragma unroll
    for (int i = 0; i < 4; i++) {
        const int t_ = c * LL + l0 + ty * 4 + i;
        *(float4*)&out[((size_t)t_ * HH + h) * DD + tx * 4] =
            make_float4(acc[i][0], acc[i][1], acc[i][2], acc[i][3]);
        if (tx == 0) row_buf[t_ * HH + h] = rowacc[i];
    }
}

// ---------------------------------------------------------------------------
// K2: symmetric-half expanded state. grid (33, H, 3), 256 threads.
// Block bt computes P[p, v] for p in [bt*64, bt*64+64), v in [0,64),
// contracting over l=1024 in tiles of 32 with smem-materialized A[p,l].
// ---------------------------------------------------------------------------
__global__ void __launch_bounds__(256, 2) pz_kernel(
    const float* __restrict__ k, const float* __restrict__ v) {
    const int bt = blockIdx.x, h = blockIdx.y, c = blockIdx.z;
    const int tid = threadIdx.x, ty = tid >> 4, tx = tid & 15;
    __shared__ float Kt[64 * 33];                 // [d][l], pad-33 for conflicts
    __shared__ __align__(16) float Vs[32 * 64];   // [l][v]
    __shared__ __align__(16) float As[32 * 64];   // A^T: [l][pp]
    __shared__ float wv[32];
    const int pp0 = tid & 63;
    const int gp = bt * 64 + pp0;
    const int d0 = lut_d[gp], e0 = lut_e[gp];
    const float m0 = lut_m[gp];
    const float gend = g_buf[(c * HH + h) * LL + LL - 1];

    float acc[4][4], zacc[4];
#pragma unroll
    for (int i = 0; i < 4; i++) {
        zacc[i] = 0.f;
#pragma unroll
        for (int j = 0; j < 4; j++) acc[i][j] = 0.f;
    }

    for (int lt = 0; lt < 32; lt++) {
        const int l0 = lt * 32;
        __syncthreads();
        for (int idx = tid; idx < 512; idx += 256) {
            int l = idx >> 4, d4 = (idx & 15) << 2;
            const size_t gb = ((size_t)(c * LL + l0 + l) * HH + h) * DD + d4;
            const float4 kv = *(const float4*)&k[gb];
            Kt[(d4 + 0) * 33 + l] = kv.x;
            Kt[(d4 + 1) * 33 + l] = kv.y;
            Kt[(d4 + 2) * 33 + l] = kv.z;
            Kt[(d4 + 3) * 33 + l] = kv.w;
            *(float4*)&Vs[l * 64 + d4] = *(const float4*)&v[gb];
        }
        if (tid < 32)
            wv[tid] = __expf(gend - g_buf[(c * HH + h) * LL + l0 + tid]);
        __syncthreads();
        // build A^T[l][pp] = m * w_l * k[l][d] * k[l][e]
#pragma unroll
        for (int u = 0; u < 8; u++) {
            const int l = (tid >> 6) + u * 4;
            As[l * 64 + pp0] = wv[l] * m0 * Kt[d0 * 33 + l] * Kt[e0 * 33 + l];
        }
        __syncthreads();
#pragma unroll 8
        for (int l = 0; l < 32; l++) {
            const float4 av = *(const float4*)&As[l * 64 + ty * 4];
            const float4 bv = *(const float4*)&Vs[l * 64 + tx * 4];
            const float a[4] = {av.x, av.y, av.z, av.w};
#pragma unroll
            for (int i = 0; i < 4; i++) {
                acc[i][0] += a[i] * bv.x;
                acc[i][1] += a[i] * bv.y;
                acc[i][2] += a[i] * bv.z;
                acc[i][3] += a[i] * bv.w;
            }
            if (tx == 0) {
#pragma unroll
                for (int i = 0; i < 4; i++) zacc[i] += a[i];
            }
        }
    }

    const size_t pb = (size_t)(c * HH + h) * PTOT + bt * 64;
#pragma unroll
    for (int i = 0; i < 4; i++)
        *(float4*)&P_buf[(pb + ty * 4 + i) * 64 + tx * 4] =
            make_float4(acc[i][0], acc[i][1], acc[i][2], acc[i][3]);
    if (tx == 0) {
#pragma unroll
        for (int i = 0; i < 4; i++) z_buf[pb + ty * 4 + i] = zacc[i];
    }
}

// ---------------------------------------------------------------------------
// K3: inter + finalize. grid (16, H, C), 256 threads.
// out[l,v] = (intra + sum_p phiQ[l,p] * S_prev[p,v]) / max(row + phiQ.z, eps)
// S_prev combined on-the-fly from up to 3 prior chunks' P.
// ---------------------------------------------------------------------------
__global__ void __launch_bounds__(256, 2) inter_kernel(
    const float* __restrict__ q, float* __restrict__ out) {
    const int tile = blockIdx.x, h = blockIdx.y, c = blockIdx.z;
    const int tid = threadIdx.x, ty = tid >> 4, tx = tid & 15;
    __shared__ float Qt[64 * 65];                 // [d][l], pad-65
    __shared__ __align__(16) float Ph[32 * 64];   // phiQ^T: [pp][l]
    __shared__ __align__(16) float Sv[32 * 64];   // [pp][v]
    __shared__ float zv[32];
    __shared__ float denl[64];
    const int l0 = tile * 64;

    float acc[4][4], dacc[4];
#pragma unroll
    for (int i = 0; i < 4; i++) {
        dacc[i] = 0.f;
#pragma unroll
        for (int j = 0; j < 4; j++) acc[i][j] = 0.f;
    }

    if (c > 0) {
        for (int idx = tid; idx < 1024; idx += 256) {
            int l = idx >> 4, d4 = (idx & 15) << 2;
            float4 qv = *(const float4*)&q[((size_t)(c * LL + l0 + l) * HH + h) * DD + d4];
            Qt[(d4 + 0) * 65 + l] = qv.x * QSCALE;
            Qt[(d4 + 1) * 65 + l] = qv.y * QSCALE;
            Qt[(d4 + 2) * 65 + l] = qv.z * QSCALE;
            Qt[(d4 + 3) * 65 + l] = qv.w * QSCALE;
        }
        const int lq = tid & 63;
        const float qdec = __expf(g_buf[(c * HH + h) * LL + l0 + lq]);
        float coef[3];
#pragma unroll
        for (int cp = 0; cp < 3; cp++) {
            float s = 0.f;
            for (int j = cp + 1; j < c; j++)
                s += g_buf[(j * HH + h) * LL + LL - 1];
            coef[cp] = __expf(s);
        }

        for (int pt = 0; pt < PTOT / 32; pt++) {
            __syncthreads();
            // stage S tile (weighted sum over prior chunks) + z tile
            for (int idx = tid; idx < 512; idx += 256) {
                int pp = idx >> 4, v4 = (idx & 15) << 2;
                float4 a4 = make_float4(0.f, 0.f, 0.f, 0.f);
                for (int cp = 0; cp < c; cp++) {
                    const float4 pv = *(const float4*)&P_buf[
                        ((size_t)(cp * HH + h) * PTOT + pt * 32 + pp) * 64 + v4];
                    a4.x += coef[cp] * pv.x;
                    a4.y += coef[cp] * pv.y;
                    a4.z += coef[cp] * pv.z;
                    a4.w += coef[cp] * pv.w;
                }
                *(float4*)&Sv[pp * 64 + v4] = a4;
            }
            if (tid < 32) {
                float a = 0.f;
                for (int cp = 0; cp < c; cp++)
                    a += coef[cp] * z_buf[(cp * HH + h) * PTOT + pt * 32 + tid];
                zv[tid] = a;
            }
            // build phiQ^T[pp][l] = qdec_l * q_l[d] * q_l[e]
#pragma unroll
            for (int u = 0; u < 8; u++) {
                const int pp = (tid >> 6) + u * 4;
                const int gp = pt * 32 + pp;
                Ph[pp * 64 + lq] =
                    qdec * Qt[lut_d[gp] * 65 + lq] * Qt[lut_e[gp] * 65 + lq];
            }
            __syncthreads();
#pragma unroll 8
            for (int pp = 0; pp < 32; pp++) {
                const float4 av = *(const float4*)&Ph[pp * 64 + ty * 4];
                const float4 bv = *(const float4*)&Sv[pp * 64 + tx * 4];
                const float a[4] = {av.x, av.y, av.z, av.w};
#pragma unroll
                for (int i = 0; i < 4; i++) {
                    acc[i][0] += a[i] * bv.x;
                    acc[i][1] += a[i] * bv.y;
                    acc[i][2] += a[i] * bv.z;
                    acc[i][3] += a[i] * bv.w;
                }
                if (tx == 0) {
                    const float zp = zv[pp];
#pragma unroll
                    for (int i = 0; i < 4; i++) dacc[i] += a[i] * zp;
                }
            }
        }
        __syncthreads();
    }

    if (tx == 0) {
#pragma unroll
        for (int i = 0; i < 4; i++) denl[ty * 4 + i] = dacc[i];
    }
    __syncthreads();

#pragma unroll
    for (int i = 0; i < 4; i++) {
        const int li = ty * 4 + i;
        const int t_ = c * LL + l0 + li;
        float den = row_buf[t_ * HH + h] + denl[li];
        den = fmaxf(den, EPSV);
        const float inv = 1.f / den;
        const size_t o = ((size_t)t_ * HH + h) * DD + tx * 4;
        float4 ov = *(float4*)&out[o];
        ov.x = (ov.x + acc[i][0]) * inv;
        ov.y = (ov.y + acc[i][1]) * inv;
        ov.z = (ov.z + acc[i][2]) * inv;
        ov.w = (ov.w + acc[i][3]) * inv;
        *(float4*)&out[o] = ov;
    }
}

extern "C" void kernel_launch(void* const* d_in, const int* in_sizes, int n_in,
                              void* d_out, int out_size) {
    const float* q = (const float*)d_in[0];
    const float* k = (const float*)d_in[1];
    const float* v = (const float*)d_in[2];
    const float* lg = (const float*)d_in[3];
    float* out = (float*)d_out;

    init_kernel<<<CC * HH + 1, 256>>>(lg);

    dim3 gt(16, HH, CC);
    intra_kernel<<<gt, 256>>>(q, k, v, out);

    dim3 gp(PTOT / 64, HH, CC - 1);
    pz_kernel<<<gp, 256>>>(k, v);

    inter_kernel<<<gt, 256>>>(q, out);
}

// round 3
// speedup vs baseline: 2.0185x; 1.0793x over previous
#include <cuda_runtime.h>

#define CC 4
#define LL 1024
#define HH 8
#define DD 64
#define TT (CC*LL)
#define QSCALE 0.125f
#define EPSV 1e-6f
#define PTOT 2112   // 2080 unique (d<=e) pairs + 32 pad
#define PREAL 2080

// Scratch (static __device__ — no allocation allowed)
__device__ float g_buf[CC*HH*LL];                 // [c][h][l] cumsum of log_g
__device__ float P_buf[(size_t)3*HH*PTOT*DD];     // [c'][h][p][v], chunks 0..2
__device__ float S_buf[(size_t)3*HH*PTOT*DD];     // prefix states for chunks 1..3
__device__ float z_buf[3*HH*PTOT];                // per-chunk normalizer
__device__ float zs_buf[3*HH*PTOT];               // prefix normalizer
__device__ float row_buf[TT*HH];                  // intra row sums
__device__ short2 lut_de[PTOT];                   // (d,e) per pair

// ---------------------------------------------------------------------------
// K0: cumsum per (c,h) + pair-LUT build (last block)
// ---------------------------------------------------------------------------
__global__ void init_kernel(const float* __restrict__ lg) {
    if (blockIdx.x == CC * HH) {
        for (int p = threadIdx.x; p < PTOT; p += 256) {
            short d = 0, e = 0;
            if (p < PREAL) {
                int off = 0, dd = 0;
                while (off + (DD - dd) <= p) { off += DD - dd; dd++; }
                d = (short)dd; e = (short)(dd + (p - off));
            }
            lut_de[p] = make_short2(d, e);
        }
        return;
    }
    int c = blockIdx.x / HH, h = blockIdx.x % HH;
    int t = threadIdx.x;
    float vloc[4];
    float s = 0.f;
#pragma unroll
    for (int i = 0; i < 4; i++) {
        int l = t * 4 + i;
        s += lg[(c * LL + l) * HH + h];
        vloc[i] = s;
    }
    float tot = s;
#pragma unroll
    for (int off = 1; off < 32; off <<= 1) {
        float n = __shfl_up_sync(0xffffffffu, tot, off);
        if ((t & 31) >= off) tot += n;
    }
    __shared__ float wsum[8];
    __shared__ float woff[8];
    if ((t & 31) == 31) wsum[t >> 5] = tot;
    __syncthreads();
    if (t == 0) {
        float a = 0.f;
        for (int w = 0; w < 8; w++) { woff[w] = a; a += wsum[w]; }
    }
    __syncthreads();
    float ex = woff[t >> 5] + (tot - s);
#pragma unroll
    for (int i = 0; i < 4; i++)
        g_buf[(c * HH + h) * LL + t * 4 + i] = ex + vloc[i];
}

// float4-group XOR swizzle (used by intra only)
__device__ __forceinline__ int swoff(int d, int r) {
    return d * 64 + ((((r >> 2) ^ (d & 15)) << 2) | (r & 3));
}

// ---------------------------------------------------------------------------
// K1: intra-chunk causal attention. grid (16, H, C), 256 threads.
// ---------------------------------------------------------------------------
__global__ void __launch_bounds__(256, 1) intra_kernel(
    const float* __restrict__ q, const float* __restrict__ k,
    const float* __restrict__ v, float* __restrict__ out) {
    const int tile = blockIdx.x, h = blockIdx.y, c = blockIdx.z;
    const int tid = threadIdx.x, ty = tid >> 4, tx = tid & 15;
    __shared__ __align__(16) float Qt[4096];
    __shared__ __align__(16) float KW[4096];
    __shared__ __align__(16) float Vs[4096];
    const int l0 = tile * 64;
    const size_t qkbase = ((size_t)(c * LL + l0) * HH + h) * DD;

    for (int i = tid; i < 1024; i += 256) {
        int l = i >> 4, d4 = (i & 15) << 2;
        const float4 qv = *(const float4*)&q[qkbase + (size_t)l * HH * DD + d4];
        Qt[swoff(d4 + 0, l)] = qv.x * QSCALE;
        Qt[swoff(d4 + 1, l)] = qv.y * QSCALE;
        Qt[swoff(d4 + 2, l)] = qv.z * QSCALE;
        Qt[swoff(d4 + 3, l)] = qv.w * QSCALE;
    }
    float gqr[4];
#pragma unroll
    for (int i = 0; i < 4; i++) gqr[i] = g_buf[(c * HH + h) * LL + l0 + ty * 4 + i];

    float acc[4][4], rowacc[4];
#pragma unroll
    for (int i = 0; i < 4; i++) {
        rowacc[i] = 0.f;
#pragma unroll
        for (int j = 0; j < 4; j++) acc[i][j] = 0.f;
    }

    for (int st = 0; st <= tile; st++) {
        const int s0 = st * 64;
        const size_t kbase = ((size_t)(c * LL + s0) * HH + h) * DD;
        __syncthreads();
        for (int i = tid; i < 1024; i += 256) {
            int s = i >> 4, d4 = (i & 15) << 2;
            const float4 kv = *(const float4*)&k[kbase + (size_t)s * HH * DD + d4];
            KW[swoff(d4 + 0, s)] = kv.x;
            KW[swoff(d4 + 1, s)] = kv.y;
            KW[swoff(d4 + 2, s)] = kv.z;
            KW[swoff(d4 + 3, s)] = kv.w;
            *(float4*)&Vs[s * 64 + d4] =
                *(const float4*)&v[kbase + (size_t)s * HH * DD + d4];
        }
        float gkr[4];
#pragma unroll
        for (int j = 0; j < 4; j++)
            gkr[j] = g_buf[(c * HH + h) * LL + s0 + tx * 4 + j];
        __syncthreads();

        float sc[4][4];
#pragma unroll
        for (int i = 0; i < 4; i++)
#pragma unroll
            for (int j = 0; j < 4; j++) sc[i][j] = 0.f;
#pragma unroll 8
        for (int d = 0; d < 64; d++) {
            const float4 av = *(const float4*)&Qt[d * 64 + ((ty ^ (d & 15)) << 2)];
            const float4 bv = *(const float4*)&KW[d * 64 + ((tx ^ (d & 15)) << 2)];
            const float a[4] = {av.x, av.y, av.z, av.w};
            const float b[4] = {bv.x, bv.y, bv.z, bv.w};
#pragma unroll
            for (int i = 0; i < 4; i++)
#pragma unroll
                for (int j = 0; j < 4; j++) sc[i][j] += a[i] * b[j];
        }
        __syncthreads();

        const bool diag = (st == tile);
#pragma unroll
        for (int i = 0; i < 4; i++) {
            float w[4];
#pragma unroll
            for (int j = 0; j < 4; j++) {
                float e = __expf(gqr[i] - gkr[j]);
                float scv = sc[i][j];
                float wv = e * scv * scv;
                if (diag && (ty * 4 + i) < (tx * 4 + j)) wv = 0.f;
                w[j] = wv;
            }
            ((float4*)&KW[(ty * 4 + i) * 64])[tx] = make_float4(w[0], w[1], w[2], w[3]);
        }
        __syncthreads();

#pragma unroll 8
        for (int s = 0; s < 64; s++) {
            float a[4];
#pragma unroll
            for (int i = 0; i < 4; i++) a[i] = KW[(ty * 4 + i) * 64 + s];
            const float4 bv = *(const float4*)&Vs[s * 64 + tx * 4];
#pragma unroll
            for (int i = 0; i < 4; i++) {
                acc[i][0] += a[i] * bv.x;
                acc[i][1] += a[i] * bv.y;
                acc[i][2] += a[i] * bv.z;
                acc[i][3] += a[i] * bv.w;
            }
            if (tx == 0) {
#pragma unroll
                for (int i = 0; i < 4; i++) rowacc[i] += a[i];
            }
        }
    }

#pragma unroll
    for (int i = 0; i < 4; i++) {
        const int t_ = c * LL + l0 + ty * 4 + i;
        *(float4*)&out[((size_t)t_ * HH + h) * DD + tx * 4] =
            make_float4(acc[i][0], acc[i][1], acc[i][2], acc[i][3]);
        if (tx == 0) row_buf[t_ * HH + h] = rowacc[i];
    }
}

// ---------------------------------------------------------------------------
// K2: symmetric-half expanded state. grid (33, H, 3), 128 threads.
// 64p x 64v tile, 8x4 micro-tile per thread.
// ---------------------------------------------------------------------------
__global__ void __launch_bounds__(128) pz_kernel(
    const float* __restrict__ k, const float* __restrict__ v) {
    const int bt = blockIdx.x, h = blockIdx.y, c = blockIdx.z;
    const int tid = threadIdx.x;
    const int ty = tid >> 4, tx = tid & 15;
    const int ppl = tid & 63, hf = tid >> 6;
    __shared__ float Kt[64 * 33];                 // [d][l], pad-33
    __shared__ __align__(16) float Vs[32 * 64];   // [l][v]
    __shared__ __align__(16) float As[32 * 64];   // [l][pp]
    __shared__ float wv[32];
    __shared__ float zps[128];
    __shared__ short2 lutS[64];
    const float gend = g_buf[(c * HH + h) * LL + LL - 1];

    if (tid < 64) lutS[tid] = lut_de[bt * 64 + tid];
    zps[tid] = 0.f;
    __syncthreads();
    const int gp = bt * 64 + ppl;
    const short2 de = lutS[ppl];
    const float m0 = (gp >= PREAL) ? 0.f : ((de.x == de.y) ? 1.f : 2.f);
    const int dK = de.x * 33, eK = de.y * 33;

    float acc[8][4];
#pragma unroll
    for (int i = 0; i < 8; i++)
#pragma unroll
        for (int j = 0; j < 4; j++) acc[i][j] = 0.f;

    for (int lt = 0; lt < 32; lt++) {
        const int l0 = lt * 32;
        __syncthreads();
        for (int idx = tid; idx < 512; idx += 128) {
            int l = idx >> 4, d4 = (idx & 15) << 2;
            const size_t gb = ((size_t)(c * LL + l0 + l) * HH + h) * DD + d4;
            const float4 kv = *(const float4*)&k[gb];
            Kt[(d4 + 0) * 33 + l] = kv.x;
            Kt[(d4 + 1) * 33 + l] = kv.y;
            Kt[(d4 + 2) * 33 + l] = kv.z;
            Kt[(d4 + 3) * 33 + l] = kv.w;
            *(float4*)&Vs[l * 64 + d4] = *(const float4*)&v[gb];
        }
        if (tid < 32)
            wv[tid] = __expf(gend - g_buf[(c * HH + h) * LL + l0 + tid]);
        __syncthreads();
#pragma unroll
        for (int u = 0; u < 16; u++) {
            const int l = hf + u * 2;
            As[l * 64 + ppl] = wv[l] * m0 * Kt[dK + l] * Kt[eK + l];
        }
        __syncthreads();
        {
            float s = 0.f;
#pragma unroll
            for (int l = hf * 16; l < hf * 16 + 16; l++) s += As[l * 64 + ppl];
            zps[tid] += s;
        }
#pragma unroll 8
        for (int l = 0; l < 32; l++) {
            const float4 a0 = *(const float4*)&As[l * 64 + ty * 8];
            const float4 a1 = *(const float4*)&As[l * 64 + ty * 8 + 4];
            const float4 bv = *(const float4*)&Vs[l * 64 + tx * 4];
            const float a[8] = {a0.x, a0.y, a0.z, a0.w, a1.x, a1.y, a1.z, a1.w};
#pragma unroll
            for (int i = 0; i < 8; i++) {
                acc[i][0] += a[i] * bv.x;
                acc[i][1] += a[i] * bv.y;
                acc[i][2] += a[i] * bv.z;
                acc[i][3] += a[i] * bv.w;
            }
        }
    }

    const size_t pb = (size_t)(c * HH + h) * PTOT + bt * 64;
#pragma unroll
    for (int i = 0; i < 8; i++)
        *(float4*)&P_buf[(pb + ty * 8 + i) * 64 + tx * 4] =
            make_float4(acc[i][0], acc[i][1], acc[i][2], acc[i][3]);
    __syncthreads();
    if (tid < 64) z_buf[pb + tid] = zps[tid] + zps[64 + tid];
}

// ---------------------------------------------------------------------------
// K2b: prefix-state combine (3-step recurrence), fully coalesced.
// ---------------------------------------------------------------------------
__global__ void combineP_kernel() {
    const int perh = PTOT * 16;   // float4 per (c,h)
    int idx = blockIdx.x * 256 + threadIdx.x;
    if (idx >= HH * perh) return;
    int h = idx / perh, r = idx % perh;
    const float gt1 = __expf(g_buf[(1 * HH + h) * LL + LL - 1]);
    const float gt2 = __expf(g_buf[(2 * HH + h) * LL + LL - 1]);
    const float4* P = (const float4*)P_buf;
    float4* S = (float4*)S_buf;
    const size_t o0 = (size_t)(0 * HH + h) * perh + r;
    const size_t o1 = (size_t)(1 * HH + h) * perh + r;
    const size_t o2 = (size_t)(2 * HH + h) * perh + r;
    const float4 p0 = P[o0], p1 = P[o1], p2 = P[o2];
    float4 s1 = p0;
    float4 s2 = make_float4(gt1 * s1.x + p1.x, gt1 * s1.y + p1.y,
                            gt1 * s1.z + p1.z, gt1 * s1.w + p1.w);
    float4 s3 = make_float4(gt2 * s2.x + p2.x, gt2 * s2.y + p2.y,
                            gt2 * s2.z + p2.z, gt2 * s2.w + p2.w);
    S[o0] = s1; S[o1] = s2; S[o2] = s3;
}

__global__ void combineZ_kernel() {
    int idx = blockIdx.x * 256 + threadIdx.x;
    if (idx >= HH * PTOT) return;
    int h = idx / PTOT, r = idx % PTOT;
    const float gt1 = __expf(g_buf[(1 * HH + h) * LL + LL - 1]);
    const float gt2 = __expf(g_buf[(2 * HH + h) * LL + LL - 1]);
    const float p0 = z_buf[(0 * HH + h) * PTOT + r];
    const float p1 = z_buf[(1 * HH + h) * PTOT + r];
    const float p2 = z_buf[(2 * HH + h) * PTOT + r];
    float s1 = p0;
    float s2 = gt1 * s1 + p1;
    float s3 = gt2 * s2 + p2;
    zs_buf[(0 * HH + h) * PTOT + r] = s1;
    zs_buf[(1 * HH + h) * PTOT + r] = s2;
    zs_buf[(2 * HH + h) * PTOT + r] = s3;
}

// ---------------------------------------------------------------------------
// K3: inter + finalize. grid (16, H, C), 128 threads, 8x4 micro-tile.
// ---------------------------------------------------------------------------
__global__ void __launch_bounds__(128) inter_kernel(
    const float* __restrict__ q, float* __restrict__ out) {
    const int tile = blockIdx.x, h = blockIdx.y, c = blockIdx.z;
    const int tid = threadIdx.x;
    const int ty = tid >> 4, tx = tid & 15;
    const int lq = tid & 63, hf = tid >> 6;
    __shared__ float Qt[64 * 65];                 // [d][l], pad-65
    __shared__ __align__(16) float Ph[32 * 64];   // [pp][l]
    __shared__ __align__(16) float Sv[32 * 64];   // [pp][v]
    __shared__ float zv[32];
    __shared__ float qd[64];
    __shared__ float denp[128];
    __shared__ float denl[64];
    __shared__ short2 lutS[PTOT];
    const int l0 = tile * 64;

    float acc[8][4];
#pragma unroll
    for (int i = 0; i < 8; i++)
#pragma unroll
        for (int j = 0; j < 4; j++) acc[i][j] = 0.f;

    if (tid < 64) denl[tid] = 0.f;

    if (c > 0) {
        for (int p = tid; p < PTOT; p += 128) lutS[p] = lut_de[p];
        for (int idx = tid; idx < 1024; idx += 128) {
            int l = idx >> 4, d4 = (idx & 15) << 2;
            float4 qv = *(const float4*)&q[((size_t)(c * LL + l0 + l) * HH + h) * DD + d4];
            Qt[(d4 + 0) * 65 + l] = qv.x * QSCALE;
            Qt[(d4 + 1) * 65 + l] = qv.y * QSCALE;
            Qt[(d4 + 2) * 65 + l] = qv.z * QSCALE;
            Qt[(d4 + 3) * 65 + l] = qv.w * QSCALE;
        }
        if (tid < 64) qd[tid] = __expf(g_buf[(c * HH + h) * LL + l0 + tid]);
        denp[tid] = 0.f;
        const float* Sp = &S_buf[(size_t)((c - 1) * HH + h) * PTOT * DD];
        const float* zp = &zs_buf[((c - 1) * HH + h) * PTOT];

        for (int pt = 0; pt < PTOT / 32; pt++) {
            __syncthreads();   // prev GEMM done with Ph/Sv
            for (int idx = tid; idx < 512; idx += 128)
                *(float4*)&Sv[idx << 2] =
                    *(const float4*)&Sp[((size_t)pt << 11) + (idx << 2)];
            if (tid < 32) zv[tid] = zp[pt * 32 + tid];
#pragma unroll
            for (int u = 0; u < 16; u++) {
                const int pp = hf + u * 2;
                const short2 de = lutS[pt * 32 + pp];
                Ph[pp * 64 + lq] =
                    qd[lq] * Qt[de.x * 65 + lq] * Qt[de.y * 65 + lq];
            }
            __syncthreads();   // Ph/Sv visible
            {
                float s = 0.f;
#pragma unroll
                for (int pp = hf * 16; pp < hf * 16 + 16; pp++)
                    s += Ph[pp * 64 + lq] * zv[pp];
                denp[tid] += s;
            }
#pragma unroll 8
            for (int pp = 0; pp < 32; pp++) {
                const float4 a0 = *(const float4*)&Ph[pp * 64 + ty * 8];
                const float4 a1 = *(const float4*)&Ph[pp * 64 + ty * 8 + 4];
                const float4 bv = *(const float4*)&Sv[pp * 64 + tx * 4];
                const float a[8] = {a0.x, a0.y, a0.z, a0.w,
                                    a1.x, a1.y, a1.z, a1.w};
#pragma unroll
                for (int i = 0; i < 8; i++) {
                    acc[i][0] += a[i] * bv.x;
                    acc[i][1] += a[i] * bv.y;
                    acc[i][2] += a[i] * bv.z;
                    acc[i][3] += a[i] * bv.w;
                }
            }
        }
        __syncthreads();
        if (tid < 64) denl[tid] = denp[tid] + denp[64 + tid];
    }
    __syncthreads();

#pragma unroll
    for (int i = 0; i < 8; i++) {
        const int li = ty * 8 + i;
        const int t_ = c * LL + l0 + li;
        float den = fmaxf(row_buf[t_ * HH + h] + denl[li], EPSV);
        const float inv = 1.f / den;
        const size_t o = ((size_t)t_ * HH + h) * DD + tx * 4;
        float4 ov = *(float4*)&out[o];
        ov.x = (ov.x + acc[i][0]) * inv;
        ov.y = (ov.y + acc[i][1]) * inv;
        ov.z = (ov.z + acc[i][2]) * inv;
        ov.w = (ov.w + acc[i][3]) * inv;
        *(float4*)&out[o] = ov;
    }
}

extern "C" void kernel_launch(void* const* d_in, const int* in_sizes, int n_in,
                              void* d_out, int out_size) {
    const float* q = (const float*)d_in[0];
    const float* k = (const float*)d_in[1];
    const float* v = (const float*)d_in[2];
    const float* lg = (const float*)d_in[3];
    float* out = (float*)d_out;

    init_kernel<<<CC * HH + 1, 256>>>(lg);

    dim3 gt(16, HH, CC);
    intra_kernel<<<gt, 256>>>(q, k, v, out);

    dim3 gp(PTOT / 64, HH, CC - 1);
    pz_kernel<<<gp, 128>>>(k, v);

    combineP_kernel<<<(HH * PTOT * 16 + 255) / 256, 256>>>();
    combineZ_kernel<<<(HH * PTOT + 255) / 256, 256>>>();

    inter_kernel<<<gt, 128>>>(q, out);
}

// round 5
// speedup vs baseline: 2.8146x; 1.3944x over previous
#include <cuda_runtime.h>
#include <cuda_bf16.h>
#include <cstdint>

#define CC 4
#define LL 1024
#define HH 8
#define DD 64
#define TT (CC*LL)
#define QSCALE 0.125f
#define EPSV 1e-6f
#define PTOT 2176   // 2080 unique (d<=e) pairs + 96 pad (17*128)
#define PREAL 2080

// Scratch (static __device__ — no allocation allowed)
__device__ float g_buf[CC*HH*LL];                 // [c][h][l] cumsum of log_g
__device__ float P_buf[(size_t)3*HH*PTOT*DD];     // [c'][h][p][v], chunks 0..2
__device__ float S_buf[(size_t)3*HH*PTOT*DD];     // prefix states for chunks 1..3
__device__ float z_buf[3*HH*PTOT];                // per-chunk normalizer
__device__ float zs_buf[3*HH*PTOT];               // prefix normalizer
__device__ float row_buf[TT*HH];                  // intra row sums
__device__ short2 lut_de[PTOT];                   // (d,e) per pair

// ---------------------------------------------------------------------------
// mma.sync helpers (sm_80-level PTX; runs on Blackwell tensor pipe)
// ---------------------------------------------------------------------------
__device__ __forceinline__ uint32_t smem_u32(const void* p) {
    uint32_t a;
    asm("{ .reg .u64 t; cvta.to.shared.u64 t, %1; cvt.u32.u64 %0, t; }"
        : "=r"(a) : "l"(p));
    return a;
}
__device__ __forceinline__ void ldsm4(uint32_t* r, uint32_t a) {
    asm volatile("ldmatrix.sync.aligned.m8n8.x4.shared.b16 {%0,%1,%2,%3}, [%4];"
        : "=r"(r[0]), "=r"(r[1]), "=r"(r[2]), "=r"(r[3]) : "r"(a));
}
__device__ __forceinline__ void ldsm4t(uint32_t* r, uint32_t a) {
    asm volatile("ldmatrix.sync.aligned.m8n8.x4.trans.shared.b16 {%0,%1,%2,%3}, [%4];"
        : "=r"(r[0]), "=r"(r[1]), "=r"(r[2]), "=r"(r[3]) : "r"(a));
}
__device__ __forceinline__ void mma16816(float* d, const uint32_t* a, const uint32_t* b) {
    asm volatile("mma.sync.aligned.m16n8k16.row.col.f32.bf16.bf16.f32 "
        "{%0,%1,%2,%3}, {%4,%5,%6,%7}, {%8,%9}, {%0,%1,%2,%3};"
        : "+f"(d[0]), "+f"(d[1]), "+f"(d[2]), "+f"(d[3])
        : "r"(a[0]), "r"(a[1]), "r"(a[2]), "r"(a[3]), "r"(b[0]), "r"(b[1]));
}
// fp32 -> (hi, lo) bf16 split store
__device__ __forceinline__ void split_st(__nv_bfloat16* hb, __nv_bfloat16* lb,
                                         int idx, float a) {
    __nv_bfloat16 hv = __float2bfloat16(a);
    hb[idx] = hv;
    lb[idx] = __float2bfloat16(a - __bfloat162float(hv));
}

// ---------------------------------------------------------------------------
// K0: cumsum per (c,h) + pair-LUT build (last block)
// ---------------------------------------------------------------------------
__global__ void init_kernel(const float* __restrict__ lg) {
    if (blockIdx.x == CC * HH) {
        for (int p = threadIdx.x; p < PTOT; p += 256) {
            short d = 0, e = 0;
            if (p < PREAL) {
                int off = 0, dd = 0;
                while (off + (DD - dd) <= p) { off += DD - dd; dd++; }
                d = (short)dd; e = (short)(dd + (p - off));
            }
            lut_de[p] = make_short2(d, e);
        }
        return;
    }
    int c = blockIdx.x / HH, h = blockIdx.x % HH;
    int t = threadIdx.x;
    float vloc[4];
    float s = 0.f;
#pragma unroll
    for (int i = 0; i < 4; i++) {
        int l = t * 4 + i;
        s += lg[(c * LL + l) * HH + h];
        vloc[i] = s;
    }
    float tot = s;
#pragma unroll
    for (int off = 1; off < 32; off <<= 1) {
        float n = __shfl_up_sync(0xffffffffu, tot, off);
        if ((t & 31) >= off) tot += n;
    }
    __shared__ float wsum[8];
    __shared__ float woff[8];
    if ((t & 31) == 31) wsum[t >> 5] = tot;
    __syncthreads();
    if (t == 0) {
        float a = 0.f;
        for (int w = 0; w < 8; w++) { woff[w] = a; a += wsum[w]; }
    }
    __syncthreads();
    float ex = woff[t >> 5] + (tot - s);
#pragma unroll
    for (int i = 0; i < 4; i++)
        g_buf[(c * HH + h) * LL + t * 4 + i] = ex + vloc[i];
}

// float4-group XOR swizzle (used by intra only)
__device__ __forceinline__ int swoff(int d, int r) {
    return d * 64 + ((((r >> 2) ^ (d & 15)) << 2) | (r & 3));
}

// ---------------------------------------------------------------------------
// K1: intra-chunk causal attention (fp32). grid (16, H, C), 256 threads.
// ---------------------------------------------------------------------------
__global__ void __launch_bounds__(256, 1) intra_kernel(
    const float* __restrict__ q, const float* __restrict__ k,
    const float* __restrict__ v, float* __restrict__ out) {
    const int tile = blockIdx.x, h = blockIdx.y, c = blockIdx.z;
    const int tid = threadIdx.x, ty = tid >> 4, tx = tid & 15;
    __shared__ __align__(16) float Qt[4096];
    __shared__ __align__(16) float KW[4096];
    __shared__ __align__(16) float Vs[4096];
    const int l0 = tile * 64;
    const size_t qkbase = ((size_t)(c * LL + l0) * HH + h) * DD;

    for (int i = tid; i < 1024; i += 256) {
        int l = i >> 4, d4 = (i & 15) << 2;
        const float4 qv = *(const float4*)&q[qkbase + (size_t)l * HH * DD + d4];
        Qt[swoff(d4 + 0, l)] = qv.x * QSCALE;
        Qt[swoff(d4 + 1, l)] = qv.y * QSCALE;
        Qt[swoff(d4 + 2, l)] = qv.z * QSCALE;
        Qt[swoff(d4 + 3, l)] = qv.w * QSCALE;
    }
    float gqr[4];
#pragma unroll
    for (int i = 0; i < 4; i++) gqr[i] = g_buf[(c * HH + h) * LL + l0 + ty * 4 + i];

    float acc[4][4], rowacc[4];
#pragma unroll
    for (int i = 0; i < 4; i++) {
        rowacc[i] = 0.f;
#pragma unroll
        for (int j = 0; j < 4; j++) acc[i][j] = 0.f;
    }

    for (int st = 0; st <= tile; st++) {
        const int s0 = st * 64;
        const size_t kbase = ((size_t)(c * LL + s0) * HH + h) * DD;
        __syncthreads();
        for (int i = tid; i < 1024; i += 256) {
            int s = i >> 4, d4 = (i & 15) << 2;
            const float4 kv = *(const float4*)&k[kbase + (size_t)s * HH * DD + d4];
            KW[swoff(d4 + 0, s)] = kv.x;
            KW[swoff(d4 + 1, s)] = kv.y;
            KW[swoff(d4 + 2, s)] = kv.z;
            KW[swoff(d4 + 3, s)] = kv.w;
            *(float4*)&Vs[s * 64 + d4] =
                *(const float4*)&v[kbase + (size_t)s * HH * DD + d4];
        }
        float gkr[4];
#pragma unroll
        for (int j = 0; j < 4; j++)
            gkr[j] = g_buf[(c * HH + h) * LL + s0 + tx * 4 + j];
        __syncthreads();

        float sc[4][4];
#pragma unroll
        for (int i = 0; i < 4; i++)
#pragma unroll
            for (int j = 0; j < 4; j++) sc[i][j] = 0.f;
#pragma unroll 8
        for (int d = 0; d < 64; d++) {
            const float4 av = *(const float4*)&Qt[d * 64 + ((ty ^ (d & 15)) << 2)];
            const float4 bv = *(const float4*)&KW[d * 64 + ((tx ^ (d & 15)) << 2)];
            const float a[4] = {av.x, av.y, av.z, av.w};
            const float b[4] = {bv.x, bv.y, bv.z, bv.w};
#pragma unroll
            for (int i = 0; i < 4; i++)
#pragma unroll
                for (int j = 0; j < 4; j++) sc[i][j] += a[i] * b[j];
        }
        __syncthreads();

        const bool diag = (st == tile);
#pragma unroll
        for (int i = 0; i < 4; i++) {
            float w[4];
#pragma unroll
            for (int j = 0; j < 4; j++) {
                float e = __expf(gqr[i] - gkr[j]);
                float scv = sc[i][j];
                float wv = e * scv * scv;
                if (diag && (ty * 4 + i) < (tx * 4 + j)) wv = 0.f;
                w[j] = wv;
            }
            ((float4*)&KW[(ty * 4 + i) * 64])[tx] = make_float4(w[0], w[1], w[2], w[3]);
        }
        __syncthreads();

#pragma unroll 8
        for (int s = 0; s < 64; s++) {
            float a[4];
#pragma unroll
            for (int i = 0; i < 4; i++) a[i] = KW[(ty * 4 + i) * 64 + s];
            const float4 bv = *(const float4*)&Vs[s * 64 + tx * 4];
#pragma unroll
            for (int i = 0; i < 4; i++) {
                acc[i][0] += a[i] * bv.x;
                acc[i][1] += a[i] * bv.y;
                acc[i][2] += a[i] * bv.z;
                acc[i][3] += a[i] * bv.w;
            }
            if (tx == 0) {
#pragma unroll
                for (int i = 0; i < 4; i++) rowacc[i] += a[i];
            }
        }
    }

#pragma unroll
    for (int i = 0; i < 4; i++) {
        const int t_ = c * LL + l0 + ty * 4 + i;
        *(float4*)&out[((size_t)t_ * HH + h) * DD + tx * 4] =
            make_float4(acc[i][0], acc[i][1], acc[i][2], acc[i][3]);
        if (tx == 0) row_buf[t_ * HH + h] = rowacc[i];
    }
}

// ---------------------------------------------------------------------------
// K2: pz via bf16-split mma.sync. grid (17, H, 3), 256 threads (8 warps).
// Block: P tile 128p x 64v; contraction over l=1024 in 32-tiles.
// ---------------------------------------------------------------------------
__global__ void __launch_bounds__(256) pz_tc_kernel(
    const float* __restrict__ k, const float* __restrict__ v) {
    __shared__ float Ks[32 * 67];                           // [l][d] fp32
    __shared__ __align__(16) __nv_bfloat16 Bh[32 * 72];     // V split hi [l][v]
    __shared__ __align__(16) __nv_bfloat16 Bl[32 * 72];
    __shared__ __align__(16) __nv_bfloat16 Ah[128 * 40];    // A split hi [p][l]
    __shared__ __align__(16) __nv_bfloat16 Al[128 * 40];
    __shared__ float wl[32];
    const int bt = blockIdx.x, h = blockIdx.y, c = blockIdx.z;
    const int tid = threadIdx.x, lane = tid & 31, w = tid >> 5;
    const int p0 = bt * 128;
    const short2 de = lut_de[p0 + (tid >> 1)];
    const float m0 = (p0 + (tid >> 1) >= PREAL) ? 0.f
                     : ((de.x == de.y) ? 1.f : 2.f);
    const int lh = (tid & 1) * 16;
    const int pr = tid >> 1;
    const float gend = g_buf[(c * HH + h) * LL + LL - 1];
    float zacc = 0.f;

    float acc[8][4];
#pragma unroll
    for (int i = 0; i < 8; i++)
#pragma unroll
        for (int j = 0; j < 4; j++) acc[i][j] = 0.f;

    const uint32_t AhB = smem_u32(Ah), AlB = smem_u32(Al);
    const uint32_t BhB = smem_u32(Bh), BlB = smem_u32(Bl);
    const int m0w = w * 16;
    const uint32_t aoff = ((m0w + (lane & 15)) * 40 + (lane >> 4) * 8) * 2;
    const uint32_t boff = ((lane & 15) * 72 + (lane >> 4) * 8) * 2;

    for (int lt = 0; lt < 32; lt++) {
        const int l0g = lt * 32;
        __syncthreads();
        for (int idx = tid; idx < 512; idx += 256) {
            int l = idx >> 4, d4 = (idx & 15) << 2;
            const size_t gb = ((size_t)(c * LL + l0g + l) * HH + h) * DD + d4;
            const float4 kv = *(const float4*)&k[gb];
            const float4 vv = *(const float4*)&v[gb];
            Ks[l * 67 + d4 + 0] = kv.x;
            Ks[l * 67 + d4 + 1] = kv.y;
            Ks[l * 67 + d4 + 2] = kv.z;
            Ks[l * 67 + d4 + 3] = kv.w;
            split_st(Bh, Bl, l * 72 + d4 + 0, vv.x);
            split_st(Bh, Bl, l * 72 + d4 + 1, vv.y);
            split_st(Bh, Bl, l * 72 + d4 + 2, vv.z);
            split_st(Bh, Bl, l * 72 + d4 + 3, vv.w);
        }
        if (tid < 32)
            wl[tid] = __expf(gend - g_buf[(c * HH + h) * LL + l0g + tid]);
        __syncthreads();
#pragma unroll
        for (int j = 0; j < 16; j++) {
            const int l = lh + j;
            const float a = m0 * wl[l] * Ks[l * 67 + de.x] * Ks[l * 67 + de.y];
            zacc += a;
            split_st(Ah, Al, pr * 40 + l, a);
        }
        __syncthreads();
#pragma unroll
        for (int ks = 0; ks < 2; ks++) {
            uint32_t ah[4], al[4];
            ldsm4(ah, AhB + aoff + ks * 32);
            ldsm4(al, AlB + aoff + ks * 32);
#pragma unroll
            for (int nt2 = 0; nt2 < 4; nt2++) {
                uint32_t bh[4], bl[4];
                const uint32_t bo = boff + ks * (16 * 72 * 2) + nt2 * 32;
                ldsm4t(bh, BhB + bo);
                ldsm4t(bl, BlB + bo);
                mma16816(acc[2 * nt2],     ah, bh);
                mma16816(acc[2 * nt2],     ah, bl);
                mma16816(acc[2 * nt2],     al, bh);
                mma16816(acc[2 * nt2 + 1], ah, bh + 2);
                mma16816(acc[2 * nt2 + 1], ah, bl + 2);
                mma16816(acc[2 * nt2 + 1], al, bh + 2);
            }
        }
    }

    const float zo = zacc + __shfl_xor_sync(0xffffffffu, zacc, 1);
    const size_t pb = (size_t)(c * HH + h) * PTOT + p0;
    if (!(tid & 1)) z_buf[pb + pr] = zo;

    const int r0 = m0w + (lane >> 2);
    float* P0 = &P_buf[(pb + r0) * 64];
    float* P1 = &P_buf[(pb + r0 + 8) * 64];
#pragma unroll
    for (int nt = 0; nt < 8; nt++) {
        const int c2 = nt * 8 + 2 * (lane & 3);
        *(float2*)&P0[c2] = make_float2(acc[nt][0], acc[nt][1]);
        *(float2*)&P1[c2] = make_float2(acc[nt][2], acc[nt][3]);
    }
}

// ---------------------------------------------------------------------------
// K2b: prefix-state combine (3-step recurrence), fully coalesced.
// ---------------------------------------------------------------------------
__global__ void combineP_kernel() {
    const int perh = PTOT * 16;   // float4 per (c,h)
    int idx = blockIdx.x * 256 + threadIdx.x;
    if (idx >= HH * perh) return;
    int h = idx / perh, r = idx % perh;
    const float gt1 = __expf(g_buf[(1 * HH + h) * LL + LL - 1]);
    const float gt2 = __expf(g_buf[(2 * HH + h) * LL + LL - 1]);
    const float4* P = (const float4*)P_buf;
    float4* S = (float4*)S_buf;
    const size_t o0 = (size_t)(0 * HH + h) * perh + r;
    const size_t o1 = (size_t)(1 * HH + h) * perh + r;
    const size_t o2 = (size_t)(2 * HH + h) * perh + r;
    const float4 p0 = P[o0], p1 = P[o1], p2 = P[o2];
    float4 s1 = p0;
    float4 s2 = make_float4(gt1 * s1.x + p1.x, gt1 * s1.y + p1.y,
                            gt1 * s1.z + p1.z, gt1 * s1.w + p1.w);
    float4 s3 = make_float4(gt2 * s2.x + p2.x, gt2 * s2.y + p2.y,
                            gt2 * s2.z + p2.z, gt2 * s2.w + p2.w);
    S[o0] = s1; S[o1] = s2; S[o2] = s3;
}

__global__ void combineZ_kernel() {
    int idx = blockIdx.x * 256 + threadIdx.x;
    if (idx >= HH * PTOT) return;
    int h = idx / PTOT, r = idx % PTOT;
    const float gt1 = __expf(g_buf[(1 * HH + h) * LL + LL - 1]);
    const float gt2 = __expf(g_buf[(2 * HH + h) * LL + LL - 1]);
    const float p0 = z_buf[(0 * HH + h) * PTOT + r];
    const float p1 = z_buf[(1 * HH + h) * PTOT + r];
    const float p2 = z_buf[(2 * HH + h) * PTOT + r];
    float s1 = p0;
    float s2 = gt1 * s1 + p1;
    float s3 = gt2 * s2 + p2;
    zs_buf[(0 * HH + h) * PTOT + r] = s1;
    zs_buf[(1 * HH + h) * PTOT + r] = s2;
    zs_buf[(2 * HH + h) * PTOT + r] = s3;
}

// ---------------------------------------------------------------------------
// K3: inter via bf16-split mma.sync + finalize. grid (16, H, C), 128 threads.
// Block: 64 l-rows x 64 v; contraction over p=2176 in 32-tiles.
// ---------------------------------------------------------------------------
__global__ void __launch_bounds__(128) inter_tc_kernel(
    const float* __restrict__ q, float* __restrict__ out) {
    const int bx = blockIdx.x, h = blockIdx.y, c = blockIdx.z;
    const int tid = threadIdx.x, lane = tid & 31, w = tid >> 5;
    const int l0 = bx * 64;

    if (c == 0) {  // finalize only: divide intra numerator by row-sum
        for (int idx = tid; idx < 1024; idx += 128) {
            int l = idx >> 4, v4 = (idx & 15) << 2;
            const int t_ = l0 + l;
            const float inv = 1.f / fmaxf(row_buf[t_ * HH + h], EPSV);
            float4 ov = *(float4*)&out[((size_t)t_ * HH + h) * DD + v4];
            ov.x *= inv; ov.y *= inv; ov.z *= inv; ov.w *= inv;
            *(float4*)&out[((size_t)t_ * HH + h) * DD + v4] = ov;
        }
        return;
    }

    __shared__ float Qs[64 * 65];                           // [l][d] fp32 scaled
    __shared__ __align__(16) __nv_bfloat16 Ah[64 * 40];     // phiQ split [l][pp]
    __shared__ __align__(16) __nv_bfloat16 Al[64 * 40];
    __shared__ __align__(16) __nv_bfloat16 Bh[32 * 72];     // S split [pp][v]
    __shared__ __align__(16) __nv_bfloat16 Bl[32 * 72];
    __shared__ float zv[32];
    __shared__ short2 lutS[32];
    __shared__ float denp[128];
    __shared__ float denl[64];

    for (int idx = tid; idx < 1024; idx += 128) {
        int l = idx >> 4, d4 = (idx & 15) << 2;
        float4 qv = *(const float4*)&q[((size_t)(c * LL + l0 + l) * HH + h) * DD + d4];
        Qs[l * 65 + d4 + 0] = qv.x * QSCALE;
        Qs[l * 65 + d4 + 1] = qv.y * QSCALE;
        Qs[l * 65 + d4 + 2] = qv.z * QSCALE;
        Qs[l * 65 + d4 + 3] = qv.w * QSCALE;
    }
    const int lrow = tid >> 1, ph = (tid & 1) * 16;
    const float qdl = __expf(g_buf[(c * HH + h) * LL + l0 + lrow]);
    float dacc = 0.f;

    float acc[8][4];
#pragma unroll
    for (int i = 0; i < 8; i++)
#pragma unroll
        for (int j = 0; j < 4; j++) acc[i][j] = 0.f;

    const float* Sp = &S_buf[(size_t)((c - 1) * HH + h) * PTOT * DD];
    const float* zp = &zs_buf[((c - 1) * HH + h) * PTOT];
    const uint32_t AhB = smem_u32(Ah), AlB = smem_u32(Al);
    const uint32_t BhB = smem_u32(Bh), BlB = smem_u32(Bl);
    const int m0w = w * 16;
    const uint32_t aoff = ((m0w + (lane & 15)) * 40 + (lane >> 4) * 8) * 2;
    const uint32_t boff = ((lane & 15) * 72 + (lane >> 4) * 8) * 2;

    for (int pt = 0; pt < PTOT / 32; pt++) {
        const int p0 = pt * 32;
        __syncthreads();
        for (int idx = tid; idx < 512; idx += 128) {
            int pp = idx >> 4, v4 = (idx & 15) << 2;
            const float4 sv = *(const float4*)&Sp[(size_t)(p0 + pp) * 64 + v4];
            split_st(Bh, Bl, pp * 72 + v4 + 0, sv.x);
            split_st(Bh, Bl, pp * 72 + v4 + 1, sv.y);
            split_st(Bh, Bl, pp * 72 + v4 + 2, sv.z);
            split_st(Bh, Bl, pp * 72 + v4 + 3, sv.w);
        }
        if (tid < 32) {
            zv[tid] = zp[p0 + tid];
            lutS[tid] = lut_de[p0 + tid];
        }
        __syncthreads();
#pragma unroll
        for (int j = 0; j < 16; j++) {
            const int pp = ph + j;
            const short2 de = lutS[pp];
            const float a = qdl * Qs[lrow * 65 + de.x] * Qs[lrow * 65 + de.y];
            dacc += a * zv[pp];
            split_st(Ah, Al, lrow * 40 + pp, a);
        }
        __syncthreads();
#pragma unroll
        for (int ks = 0; ks < 2; ks++) {
            uint32_t ah[4], al[4];
            ldsm4(ah, AhB + aoff + ks * 32);
            ldsm4(al, AlB + aoff + ks * 32);
#pragma unroll
            for (int nt2 = 0; nt2 < 4; nt2++) {
                uint32_t bh[4], bl[4];
                const uint32_t bo = boff + ks * (16 * 72 * 2) + nt2 * 32;
                ldsm4t(bh, BhB + bo);
                ldsm4t(bl, BlB + bo);
                mma16816(acc[2 * nt2],     ah, bh);
                mma16816(acc[2 * nt2],     ah, bl);
                mma16816(acc[2 * nt2],     al, bh);
                mma16816(acc[2 * nt2 + 1], ah, bh + 2);
                mma16816(acc[2 * nt2 + 1], ah, bl + 2);
                mma16816(acc[2 * nt2 + 1], al, bh + 2);
            }
        }
    }

    denp[tid] = dacc;
    __syncthreads();
    if (tid < 64) denl[tid] = denp[2 * tid] + denp[2 * tid + 1];
    __syncthreads();

    const int r0 = m0w + (lane >> 2);
    const int t0 = c * LL + l0 + r0, t1 = t0 + 8;
    const float inv0 = 1.f / fmaxf(row_buf[t0 * HH + h] + denl[r0], EPSV);
    const float inv1 = 1.f / fmaxf(row_buf[t1 * HH + h] + denl[r0 + 8], EPSV);
    float* O0 = &out[((size_t)t0 * HH + h) * DD];
    float* O1 = &out[((size_t)t1 * HH + h) * DD];
#pragma unroll
    for (int nt = 0; nt < 8; nt++) {
        const int c2 = nt * 8 + 2 * (lane & 3);
        float2 o0 = *(float2*)&O0[c2];
        o0.x = (o0.x + acc[nt][0]) * inv0;
        o0.y = (o0.y + acc[nt][1]) * inv0;
        *(float2*)&O0[c2] = o0;
        float2 o1 = *(float2*)&O1[c2];
        o1.x = (o1.x + acc[nt][2]) * inv1;
        o1.y = (o1.y + acc[nt][3]) * inv1;
        *(float2*)&O1[c2] = o1;
    }
}

extern "C" void kernel_launch(void* const* d_in, const int* in_sizes, int n_in,
                              void* d_out, int out_size) {
    const float* q = (const float*)d_in[0];
    const float* k = (const float*)d_in[1];
    const float* v = (const float*)d_in[2];
    const float* lg = (const float*)d_in[3];
    float* out = (float*)d_out;

    init_kernel<<<CC * HH + 1, 256>>>(lg);

    dim3 gt(16, HH, CC);
    intra_kernel<<<gt, 256>>>(q, k, v, out);

    dim3 gp(PTOT / 128, HH, CC - 1);
    pz_tc_kernel<<<gp, 256>>>(k, v);

    combineP_kernel<<<(HH * PTOT * 16 + 255) / 256, 256>>>();
    combineZ_kernel<<<(HH * PTOT + 255) / 256, 256>>>();

    dim3 gi(16, HH, CC);
    inter_tc_kernel<<<gi, 128>>>(q, out);
}

// round 6
// speedup vs baseline: 3.8667x; 1.3738x over previous
#include <cuda_runtime.h>
#include <cuda_bf16.h>
#include <cstdint>

#define CC 4
#define LL 1024
#define HH 8
#define DD 64
#define TT (CC*LL)
#define QSCALE 0.125f
#define EPSV 1e-6f
#define PTOT 2176   // 2080 unique (d<=e) pairs + 96 pad (17*128)
#define PREAL 2080

// Scratch (static __device__ — no allocation allowed)
__device__ float g_buf[CC*HH*LL];                 // [c][h][l] cumsum of log_g
__device__ float P_buf[(size_t)3*HH*PTOT*DD];     // [c'][h][p][v], chunks 0..2
__device__ float S_buf[(size_t)3*HH*PTOT*DD];     // prefix states for chunks 1..3
__device__ float z_buf[3*HH*PTOT];                // per-chunk normalizer
__device__ float zs_buf[3*HH*PTOT];               // prefix normalizer
__device__ float row_buf[TT*HH];                  // intra row sums
__device__ short2 lut_de[PTOT];                   // (d,e) per pair

// ---------------------------------------------------------------------------
// mma.sync helpers (sm_80-level PTX; runs on Blackwell tensor pipe)
// ---------------------------------------------------------------------------
__device__ __forceinline__ uint32_t smem_u32(const void* p) {
    uint32_t a;
    asm("{ .reg .u64 t; cvta.to.shared.u64 t, %1; cvt.u32.u64 %0, t; }"
        : "=r"(a) : "l"(p));
    return a;
}
__device__ __forceinline__ void ldsm4(uint32_t* r, uint32_t a) {
    asm volatile("ldmatrix.sync.aligned.m8n8.x4.shared.b16 {%0,%1,%2,%3}, [%4];"
        : "=r"(r[0]), "=r"(r[1]), "=r"(r[2]), "=r"(r[3]) : "r"(a));
}
__device__ __forceinline__ void ldsm4t(uint32_t* r, uint32_t a) {
    asm volatile("ldmatrix.sync.aligned.m8n8.x4.trans.shared.b16 {%0,%1,%2,%3}, [%4];"
        : "=r"(r[0]), "=r"(r[1]), "=r"(r[2]), "=r"(r[3]) : "r"(a));
}
__device__ __forceinline__ void mma16816(float* d, const uint32_t* a, const uint32_t* b) {
    asm volatile("mma.sync.aligned.m16n8k16.row.col.f32.bf16.bf16.f32 "
        "{%0,%1,%2,%3}, {%4,%5,%6,%7}, {%8,%9}, {%0,%1,%2,%3};"
        : "+f"(d[0]), "+f"(d[1]), "+f"(d[2]), "+f"(d[3])
        : "r"(a[0]), "r"(a[1]), "r"(a[2]), "r"(a[3]), "r"(b[0]), "r"(b[1]));
}
__device__ __forceinline__ void mma16816s(float* d, const uint32_t* a,
                                          uint32_t b0, uint32_t b1) {
    asm volatile("mma.sync.aligned.m16n8k16.row.col.f32.bf16.bf16.f32 "
        "{%0,%1,%2,%3}, {%4,%5,%6,%7}, {%8,%9}, {%0,%1,%2,%3};"
        : "+f"(d[0]), "+f"(d[1]), "+f"(d[2]), "+f"(d[3])
        : "r"(a[0]), "r"(a[1]), "r"(a[2]), "r"(a[3]), "r"(b0), "r"(b1));
}
// fp32 -> (hi, lo) bf16 split store
__device__ __forceinline__ void split_st(__nv_bfloat16* hb, __nv_bfloat16* lb,
                                         int idx, float a) {
    __nv_bfloat16 hv = __float2bfloat16(a);
    hb[idx] = hv;
    lb[idx] = __float2bfloat16(a - __bfloat162float(hv));
}
// split two floats into packed bf16x2 hi and lo words (x low half, y high half)
__device__ __forceinline__ void split2(float x, float y, uint32_t& hi, uint32_t& lo) {
    __nv_bfloat16 xh = __float2bfloat16(x), yh = __float2bfloat16(y);
    __nv_bfloat16 xl = __float2bfloat16(x - __bfloat162float(xh));
    __nv_bfloat16 yl = __float2bfloat16(y - __bfloat162float(yh));
    hi = (uint32_t)*(uint16_t*)&xh | ((uint32_t)*(uint16_t*)&yh << 16);
    lo = (uint32_t)*(uint16_t*)&xl | ((uint32_t)*(uint16_t*)&yl << 16);
}

// ---------------------------------------------------------------------------
// K0: cumsum per (c,h) + pair-LUT build (last block)
// ---------------------------------------------------------------------------
__global__ void init_kernel(const float* __restrict__ lg) {
    if (blockIdx.x == CC * HH) {
        for (int p = threadIdx.x; p < PTOT; p += 256) {
            short d = 0, e = 0;
            if (p < PREAL) {
                int off = 0, dd = 0;
                while (off + (DD - dd) <= p) { off += DD - dd; dd++; }
                d = (short)dd; e = (short)(dd + (p - off));
            }
            lut_de[p] = make_short2(d, e);
        }
        return;
    }
    int c = blockIdx.x / HH, h = blockIdx.x % HH;
    int t = threadIdx.x;
    float vloc[4];
    float s = 0.f;
#pragma unroll
    for (int i = 0; i < 4; i++) {
        int l = t * 4 + i;
        s += lg[(c * LL + l) * HH + h];
        vloc[i] = s;
    }
    float tot = s;
#pragma unroll
    for (int off = 1; off < 32; off <<= 1) {
        float n = __shfl_up_sync(0xffffffffu, tot, off);
        if ((t & 31) >= off) tot += n;
    }
    __shared__ float wsum[8];
    __shared__ float woff[8];
    if ((t & 31) == 31) wsum[t >> 5] = tot;
    __syncthreads();
    if (t == 0) {
        float a = 0.f;
        for (int w = 0; w < 8; w++) { woff[w] = a; a += wsum[w]; }
    }
    __syncthreads();
    float ex = woff[t >> 5] + (tot - s);
#pragma unroll
    for (int i = 0; i < 4; i++)
        g_buf[(c * HH + h) * LL + t * 4 + i] = ex + vloc[i];
}

// ---------------------------------------------------------------------------
// K1: intra-chunk causal attention via bf16-split mma.sync.
// grid (16, H, C), 128 threads (4 warps). Block: 64 l-rows x 64 v.
// s contraction in 32-wide subtiles; W kept in registers (FA2 repack).
// ---------------------------------------------------------------------------
__global__ void __launch_bounds__(128) intra_tc_kernel(
    const float* __restrict__ q, const float* __restrict__ k,
    const float* __restrict__ v, float* __restrict__ out) {
    __shared__ __align__(16) __nv_bfloat16 Qh[64 * 72], Ql[64 * 72];
    __shared__ __align__(16) __nv_bfloat16 Kh[32 * 72], Kl[32 * 72];
    __shared__ __align__(16) __nv_bfloat16 Vh[32 * 72], Vl[32 * 72];
    __shared__ float eqs[64], eks[32];
    const int tile = blockIdx.x, h = blockIdx.y, c = blockIdx.z;
    const int tid = threadIdx.x, lane = tid & 31, w = tid >> 5;
    const int l0 = tile * 64;
    const size_t gqb = ((size_t)(c * LL + l0) * HH + h) * DD;

    for (int idx = tid; idx < 1024; idx += 128) {
        int l = idx >> 4, d4 = (idx & 15) << 2;
        const float4 qv = *(const float4*)&q[gqb + (size_t)l * HH * DD + d4];
        split_st(Qh, Ql, l * 72 + d4 + 0, qv.x * QSCALE);
        split_st(Qh, Ql, l * 72 + d4 + 1, qv.y * QSCALE);
        split_st(Qh, Ql, l * 72 + d4 + 2, qv.z * QSCALE);
        split_st(Qh, Ql, l * 72 + d4 + 3, qv.w * QSCALE);
    }
    if (tid < 64) eqs[tid] = __expf(g_buf[(c * HH + h) * LL + l0 + tid]);

    const int m0w = w * 16;
    const int r0 = m0w + (lane >> 2);
    const uint32_t QhB = smem_u32(Qh), QlB = smem_u32(Ql);
    const uint32_t KhB = smem_u32(Kh), KlB = smem_u32(Kl);
    const uint32_t VhB = smem_u32(Vh), VlB = smem_u32(Vl);
    const uint32_t aoffQ = ((m0w + (lane & 15)) * 72 + (lane >> 4) * 8) * 2;
    const uint32_t boff = ((lane & 15) * 72 + (lane >> 4) * 8) * 2;

    float oacc[8][4];
#pragma unroll
    for (int i = 0; i < 8; i++)
#pragma unroll
        for (int j = 0; j < 4; j++) oacc[i][j] = 0.f;
    float rs0 = 0.f, rs1 = 0.f;

    const int nst = 2 * (tile + 1);
    for (int st = 0; st < nst; st++) {
        __syncthreads();
        for (int idx = tid; idx < 512; idx += 128) {
            int l = idx >> 4, d4 = (idx & 15) << 2;
            const size_t gb = ((size_t)(c * LL + st * 32 + l) * HH + h) * DD + d4;
            const float4 kv = *(const float4*)&k[gb];
            const float4 vv = *(const float4*)&v[gb];
            split_st(Kh, Kl, l * 72 + d4 + 0, kv.x);
            split_st(Kh, Kl, l * 72 + d4 + 1, kv.y);
            split_st(Kh, Kl, l * 72 + d4 + 2, kv.z);
            split_st(Kh, Kl, l * 72 + d4 + 3, kv.w);
            split_st(Vh, Vl, l * 72 + d4 + 0, vv.x);
            split_st(Vh, Vl, l * 72 + d4 + 1, vv.y);
            split_st(Vh, Vl, l * 72 + d4 + 2, vv.z);
            split_st(Vh, Vl, l * 72 + d4 + 3, vv.w);
        }
        if (tid < 32) eks[tid] = __expf(-g_buf[(c * HH + h) * LL + st * 32 + tid]);
        __syncthreads();

        // GEMM1: scores[l][s] over d (K stored [s][d] -> non-trans ldsm pairs {0,2},{1,3})
        float sc[4][4];
#pragma unroll
        for (int i = 0; i < 4; i++)
#pragma unroll
            for (int j = 0; j < 4; j++) sc[i][j] = 0.f;
#pragma unroll
        for (int kd = 0; kd < 4; kd++) {
            uint32_t ah[4], al[4];
            ldsm4(ah, QhB + aoffQ + kd * 32);
            ldsm4(al, QlB + aoffQ + kd * 32);
#pragma unroll
            for (int ng = 0; ng < 2; ng++) {
                uint32_t kh4[4], kl4[4];
                const uint32_t rb = (uint32_t)(ng * 16 * 72 * 2) + boff + kd * 32;
                ldsm4(kh4, KhB + rb);
                ldsm4(kl4, KlB + rb);
                mma16816s(sc[ng * 2],     ah, kh4[0], kh4[2]);
                mma16816s(sc[ng * 2],     ah, kl4[0], kl4[2]);
                mma16816s(sc[ng * 2],     al, kh4[0], kh4[2]);
                mma16816s(sc[ng * 2 + 1], ah, kh4[1], kh4[3]);
                mma16816s(sc[ng * 2 + 1], ah, kl4[1], kl4[3]);
                mma16816s(sc[ng * 2 + 1], al, kh4[1], kh4[3]);
            }
        }

        // elementwise weight + causal mask + register repack to A-operand
        const float eq0 = eqs[r0], eq1 = eqs[r0 + 8];
        const int soff = st * 32 - l0;
        uint32_t wah[2][4], wal[2][4];
#pragma unroll
        for (int nt = 0; nt < 4; nt++) {
            const int sA = nt * 8 + 2 * (lane & 3);
            const float ekA = eks[sA], ekB = eks[sA + 1];
            float w00 = eq0 * ekA * sc[nt][0] * sc[nt][0];
            float w01 = eq0 * ekB * sc[nt][1] * sc[nt][1];
            float w10 = eq1 * ekA * sc[nt][2] * sc[nt][2];
            float w11 = eq1 * ekB * sc[nt][3] * sc[nt][3];
            if (soff >= 0) {
                if (r0 < soff + sA) w00 = 0.f;
                if (r0 < soff + sA + 1) w01 = 0.f;
                if (r0 + 8 < soff + sA) w10 = 0.f;
                if (r0 + 8 < soff + sA + 1) w11 = 0.f;
            }
            rs0 += w00 + w01;
            rs1 += w10 + w11;
            const int ks = nt >> 1, hf2 = (nt & 1) * 2;
            split2(w00, w01, wah[ks][hf2], wal[ks][hf2]);
            split2(w10, w11, wah[ks][hf2 + 1], wal[ks][hf2 + 1]);
        }

        // GEMM2: O += W * V (V [s][v] -> trans ldsm pairs {0,1},{2,3})
#pragma unroll
        for (int ks = 0; ks < 2; ks++) {
#pragma unroll
            for (int nv = 0; nv < 4; nv++) {
                uint32_t vh4[4], vl4[4];
                const uint32_t bo = boff + (uint32_t)(ks * 16 * 72 * 2) + nv * 32;
                ldsm4t(vh4, VhB + bo);
                ldsm4t(vl4, VlB + bo);
                mma16816s(oacc[nv * 2],     wah[ks], vh4[0], vh4[1]);
                mma16816s(oacc[nv * 2],     wah[ks], vl4[0], vl4[1]);
                mma16816s(oacc[nv * 2],     wal[ks], vh4[0], vh4[1]);
                mma16816s(oacc[nv * 2 + 1], wah[ks], vh4[2], vh4[3]);
                mma16816s(oacc[nv * 2 + 1], wah[ks], vl4[2], vl4[3]);
                mma16816s(oacc[nv * 2 + 1], wal[ks], vh4[2], vh4[3]);
            }
        }
    }

    rs0 += __shfl_xor_sync(0xffffffffu, rs0, 1);
    rs0 += __shfl_xor_sync(0xffffffffu, rs0, 2);
    rs1 += __shfl_xor_sync(0xffffffffu, rs1, 1);
    rs1 += __shfl_xor_sync(0xffffffffu, rs1, 2);
    const int t0 = c * LL + l0 + r0, t1 = t0 + 8;
    if ((lane & 3) == 0) {
        row_buf[t0 * HH + h] = rs0;
        row_buf[t1 * HH + h] = rs1;
    }
    float* O0 = &out[((size_t)t0 * HH + h) * DD];
    float* O1 = &out[((size_t)t1 * HH + h) * DD];
#pragma unroll
    for (int nt = 0; nt < 8; nt++) {
        const int c2 = nt * 8 + 2 * (lane & 3);
        *(float2*)&O0[c2] = make_float2(oacc[nt][0], oacc[nt][1]);
        *(float2*)&O1[c2] = make_float2(oacc[nt][2], oacc[nt][3]);
    }
}

// ---------------------------------------------------------------------------
// K2: pz via bf16-split mma.sync. grid (17, H, 3), 256 threads (8 warps).
// Block: P tile 128p x 64v; contraction over l=1024 in 32-tiles.
// ---------------------------------------------------------------------------
__global__ void __launch_bounds__(256) pz_tc_kernel(
    const float* __restrict__ k, const float* __restrict__ v) {
    __shared__ float Ks[32 * 67];                           // [l][d] fp32
    __shared__ __align__(16) __nv_bfloat16 Bh[32 * 72];     // V split hi [l][v]
    __shared__ __align__(16) __nv_bfloat16 Bl[32 * 72];
    __shared__ __align__(16) __nv_bfloat16 Ah[128 * 40];    // A split hi [p][l]
    __shared__ __align__(16) __nv_bfloat16 Al[128 * 40];
    __shared__ float wl[32];
    const int bt = blockIdx.x, h = blockIdx.y, c = blockIdx.z;
    const int tid = threadIdx.x, lane = tid & 31, w = tid >> 5;
    const int p0 = bt * 128;
    const short2 de = lut_de[p0 + (tid >> 1)];
    const float m0 = (p0 + (tid >> 1) >= PREAL) ? 0.f
                     : ((de.x == de.y) ? 1.f : 2.f);
    const int lh = (tid & 1) * 16;
    const int pr = tid >> 1;
    const float gend = g_buf[(c * HH + h) * LL + LL - 1];
    float zacc = 0.f;

    float acc[8][4];
#pragma unroll
    for (int i = 0; i < 8; i++)
#pragma unroll
        for (int j = 0; j < 4; j++) acc[i][j] = 0.f;

    const uint32_t AhB = smem_u32(Ah), AlB = smem_u32(Al);
    const uint32_t BhB = smem_u32(Bh), BlB = smem_u32(Bl);
    const int m0w = w * 16;
    const uint32_t aoff = ((m0w + (lane & 15)) * 40 + (lane >> 4) * 8) * 2;
    const uint32_t boff = ((lane & 15) * 72 + (lane >> 4) * 8) * 2;

    for (int lt = 0; lt < 32; lt++) {
        const int l0g = lt * 32;
        __syncthreads();
        for (int idx = tid; idx < 512; idx += 256) {
            int l = idx >> 4, d4 = (idx & 15) << 2;
            const size_t gb = ((size_t)(c * LL + l0g + l) * HH + h) * DD + d4;
            const float4 kv = *(const float4*)&k[gb];
            const float4 vv = *(const float4*)&v[gb];
            Ks[l * 67 + d4 + 0] = kv.x;
            Ks[l * 67 + d4 + 1] = kv.y;
            Ks[l * 67 + d4 + 2] = kv.z;
            Ks[l * 67 + d4 + 3] = kv.w;
            split_st(Bh, Bl, l * 72 + d4 + 0, vv.x);
            split_st(Bh, Bl, l * 72 + d4 + 1, vv.y);
            split_st(Bh, Bl, l * 72 + d4 + 2, vv.z);
            split_st(Bh, Bl, l * 72 + d4 + 3, vv.w);
        }
        if (tid < 32)
            wl[tid] = __expf(gend - g_buf[(c * HH + h) * LL + l0g + tid]);
        __syncthreads();
#pragma unroll
        for (int j = 0; j < 16; j++) {
            const int l = lh + j;
            const float a = m0 * wl[l] * Ks[l * 67 + de.x] * Ks[l * 67 + de.y];
            zacc += a;
            split_st(Ah, Al, pr * 40 + l, a);
        }
        __syncthreads();
#pragma unroll
        for (int ks = 0; ks < 2; ks++) {
            uint32_t ah[4], al[4];
            ldsm4(ah, AhB + aoff + ks * 32);
            ldsm4(al, AlB + aoff + ks * 32);
#pragma unroll
            for (int nt2 = 0; nt2 < 4; nt2++) {
                uint32_t bh[4], bl[4];
                const uint32_t bo = boff + ks * (16 * 72 * 2) + nt2 * 32;
                ldsm4t(bh, BhB + bo);
                ldsm4t(bl, BlB + bo);
                mma16816(acc[2 * nt2],     ah, bh);
                mma16816(acc[2 * nt2],     ah, bl);
                mma16816(acc[2 * nt2],     al, bh);
                mma16816(acc[2 * nt2 + 1], ah, bh + 2);
                mma16816(acc[2 * nt2 + 1], ah, bl + 2);
                mma16816(acc[2 * nt2 + 1], al, bh + 2);
            }
        }
    }

    const float zo = zacc + __shfl_xor_sync(0xffffffffu, zacc, 1);
    const size_t pb = (size_t)(c * HH + h) * PTOT + p0;
    if (!(tid & 1)) z_buf[pb + pr] = zo;

    const int r0 = m0w + (lane >> 2);
    float* P0 = &P_buf[(pb + r0) * 64];
    float* P1 = &P_buf[(pb + r0 + 8) * 64];
#pragma unroll
    for (int nt = 0; nt < 8; nt++) {
        const int c2 = nt * 8 + 2 * (lane & 3);
        *(float2*)&P0[c2] = make_float2(acc[nt][0], acc[nt][1]);
        *(float2*)&P1[c2] = make_float2(acc[nt][2], acc[nt][3]);
    }
}

// ---------------------------------------------------------------------------
// K2b: prefix-state combine (3-step recurrence), fully coalesced.
// ---------------------------------------------------------------------------
__global__ void combineP_kernel() {
    const int perh = PTOT * 16;   // float4 per (c,h)
    int idx = blockIdx.x * 256 + threadIdx.x;
    if (idx >= HH * perh) return;
    int h = idx / perh, r = idx % perh;
    const float gt1 = __expf(g_buf[(1 * HH + h) * LL + LL - 1]);
    const float gt2 = __expf(g_buf[(2 * HH + h) * LL + LL - 1]);
    const float4* P = (const float4*)P_buf;
    float4* S = (float4*)S_buf;
    const size_t o0 = (size_t)(0 * HH + h) * perh + r;
    const size_t o1 = (size_t)(1 * HH + h) * perh + r;
    const size_t o2 = (size_t)(2 * HH + h) * perh + r;
    const float4 p0 = P[o0], p1 = P[o1], p2 = P[o2];
    float4 s1 = p0;
    float4 s2 = make_float4(gt1 * s1.x + p1.x, gt1 * s1.y + p1.y,
                            gt1 * s1.z + p1.z, gt1 * s1.w + p1.w);
    float4 s3 = make_float4(gt2 * s2.x + p2.x, gt2 * s2.y + p2.y,
                            gt2 * s2.z + p2.z, gt2 * s2.w + p2.w);
    S[o0] = s1; S[o1] = s2; S[o2] = s3;
}

__global__ void combineZ_kernel() {
    int idx = blockIdx.x * 256 + threadIdx.x;
    if (idx >= HH * PTOT) return;
    int h = idx / PTOT, r = idx % PTOT;
    const float gt1 = __expf(g_buf[(1 * HH + h) * LL + LL - 1]);
    const float gt2 = __expf(g_buf[(2 * HH + h) * LL + LL - 1]);
    const float p0 = z_buf[(0 * HH + h) * PTOT + r];
    const float p1 = z_buf[(1 * HH + h) * PTOT + r];
    const float p2 = z_buf[(2 * HH + h) * PTOT + r];
    float s1 = p0;
    float s2 = gt1 * s1 + p1;
    float s3 = gt2 * s2 + p2;
    zs_buf[(0 * HH + h) * PTOT + r] = s1;
    zs_buf[(1 * HH + h) * PTOT + r] = s2;
    zs_buf[(2 * HH + h) * PTOT + r] = s3;
}

// ---------------------------------------------------------------------------
// K3: inter via bf16-split mma.sync + finalize. grid (16, H, C), 128 threads.
// Block: 64 l-rows x 64 v; contraction over p=2176 in 32-tiles.
// ---------------------------------------------------------------------------
__global__ void __launch_bounds__(128) inter_tc_kernel(
    const float* __restrict__ q, float* __restrict__ out) {
    const int bx = blockIdx.x, h = blockIdx.y, c = blockIdx.z;
    const int tid = threadIdx.x, lane = tid & 31, w = tid >> 5;
    const int l0 = bx * 64;

    if (c == 0) {  // finalize only: divide intra numerator by row-sum
        for (int idx = tid; idx < 1024; idx += 128) {
            int l = idx >> 4, v4 = (idx & 15) << 2;
            const int t_ = l0 + l;
            const float inv = 1.f / fmaxf(row_buf[t_ * HH + h], EPSV);
            float4 ov = *(float4*)&out[((size_t)t_ * HH + h) * DD + v4];
            ov.x *= inv; ov.y *= inv; ov.z *= inv; ov.w *= inv;
            *(float4*)&out[((size_t)t_ * HH + h) * DD + v4] = ov;
        }
        return;
    }

    __shared__ float Qs[64 * 65];                           // [l][d] fp32 scaled
    __shared__ __align__(16) __nv_bfloat16 Ah[64 * 40];     // phiQ split [l][pp]
    __shared__ __align__(16) __nv_bfloat16 Al[64 * 40];
    __shared__ __align__(16) __nv_bfloat16 Bh[32 * 72];     // S split [pp][v]
    __shared__ __align__(16) __nv_bfloat16 Bl[32 * 72];
    __shared__ float zv[32];
    __shared__ short2 lutS[32];
    __shared__ float denp[128];
    __shared__ float denl[64];

    for (int idx = tid; idx < 1024; idx += 128) {
        int l = idx >> 4, d4 = (idx & 15) << 2;
        float4 qv = *(const float4*)&q[((size_t)(c * LL + l0 + l) * HH + h) * DD + d4];
        Qs[l * 65 + d4 + 0] = qv.x * QSCALE;
        Qs[l * 65 + d4 + 1] = qv.y * QSCALE;
        Qs[l * 65 + d4 + 2] = qv.z * QSCALE;
        Qs[l * 65 + d4 + 3] = qv.w * QSCALE;
    }
    const int lrow = tid >> 1, ph = (tid & 1) * 16;
    const float qdl = __expf(g_buf[(c * HH + h) * LL + l0 + lrow]);
    float dacc = 0.f;

    float acc[8][4];
#pragma unroll
    for (int i = 0; i < 8; i++)
#pragma unroll
        for (int j = 0; j < 4; j++) acc[i][j] = 0.f;

    const float* Sp = &S_buf[(size_t)((c - 1) * HH + h) * PTOT * DD];
    const float* zp = &zs_buf[((c - 1) * HH + h) * PTOT];
    const uint32_t AhB = smem_u32(Ah), AlB = smem_u32(Al);
    const uint32_t BhB = smem_u32(Bh), BlB = smem_u32(Bl);
    const int m0w = w * 16;
    const uint32_t aoff = ((m0w + (lane & 15)) * 40 + (lane >> 4) * 8) * 2;
    const uint32_t boff = ((lane & 15) * 72 + (lane >> 4) * 8) * 2;

    for (int pt = 0; pt < PTOT / 32; pt++) {
        const int p0 = pt * 32;
        __syncthreads();
        for (int idx = tid; idx < 512; idx += 128) {
            int pp = idx >> 4, v4 = (idx & 15) << 2;
            const float4 sv = *(const float4*)&Sp[(size_t)(p0 + pp) * 64 + v4];
            split_st(Bh, Bl, pp * 72 + v4 + 0, sv.x);
            split_st(Bh, Bl, pp * 72 + v4 + 1, sv.y);
            split_st(Bh, Bl, pp * 72 + v4 + 2, sv.z);
            split_st(Bh, Bl, pp * 72 + v4 + 3, sv.w);
        }
        if (tid < 32) {
            zv[tid] = zp[p0 + tid];
            lutS[tid] = lut_de[p0 + tid];
        }
        __syncthreads();
#pragma unroll
        for (int j = 0; j < 16; j++) {
            const int pp = ph + j;
            const short2 de = lutS[pp];
            const float a = qdl * Qs[lrow * 65 + de.x] * Qs[lrow * 65 + de.y];
            dacc += a * zv[pp];
            split_st(Ah, Al, lrow * 40 + pp, a);
        }
        __syncthreads();
#pragma unroll
        for (int ks = 0; ks < 2; ks++) {
            uint32_t ah[4], al[4];
            ldsm4(ah, AhB + aoff + ks * 32);
            ldsm4(al, AlB + aoff + ks * 32);
#pragma unroll
            for (int nt2 = 0; nt2 < 4; nt2++) {
                uint32_t bh[4], bl[4];
                const uint32_t bo = boff + ks * (16 * 72 * 2) + nt2 * 32;
                ldsm4t(bh, BhB + bo);
                ldsm4t(bl, BlB + bo);
                mma16816(acc[2 * nt2],     ah, bh);
                mma16816(acc[2 * nt2],     ah, bl);
                mma16816(acc[2 * nt2],     al, bh);
                mma16816(acc[2 * nt2 + 1], ah, bh + 2);
                mma16816(acc[2 * nt2 + 1], ah, bl + 2);
                mma16816(acc[2 * nt2 + 1], al, bh + 2);
            }
        }
    }

    denp[tid] = dacc;
    __syncthreads();
    if (tid < 64) denl[tid] = denp[2 * tid] + denp[2 * tid + 1];
    __syncthreads();

    const int r0 = m0w + (lane >> 2);
    const int t0 = c * LL + l0 + r0, t1 = t0 + 8;
    const float inv0 = 1.f / fmaxf(row_buf[t0 * HH + h] + denl[r0], EPSV);
    const float inv1 = 1.f / fmaxf(row_buf[t1 * HH + h] + denl[r0 + 8], EPSV);
    float* O0 = &out[((size_t)t0 * HH + h) * DD];
    float* O1 = &out[((size_t)t1 * HH + h) * DD];
#pragma unroll
    for (int nt = 0; nt < 8; nt++) {
        const int c2 = nt * 8 + 2 * (lane & 3);
        float2 o0 = *(float2*)&O0[c2];
        o0.x = (o0.x + acc[nt][0]) * inv0;
        o0.y = (o0.y + acc[nt][1]) * inv0;
        *(float2*)&O0[c2] = o0;
        float2 o1 = *(float2*)&O1[c2];
        o1.x = (o1.x + acc[nt][2]) * inv1;
        o1.y = (o1.y + acc[nt][3]) * inv1;
        *(float2*)&O1[c2] = o1;
    }
}

extern "C" void kernel_launch(void* const* d_in, const int* in_sizes, int n_in,
                              void* d_out, int out_size) {
    const float* q = (const float*)d_in[0];
    const float* k = (const float*)d_in[1];
    const float* v = (const float*)d_in[2];
    const float* lg = (const float*)d_in[3];
    float* out = (float*)d_out;

    init_kernel<<<CC * HH + 1, 256>>>(lg);

    dim3 gt(16, HH, CC);
    intra_tc_kernel<<<gt, 128>>>(q, k, v, out);

    dim3 gp(PTOT / 128, HH, CC - 1);
    pz_tc_kernel<<<gp, 256>>>(k, v);

    combineP_kernel<<<(HH * PTOT * 16 + 255) / 256, 256>>>();
    combineZ_kernel<<<(HH * PTOT + 255) / 256, 256>>>();

    dim3 gi(16, HH, CC);
    inter_tc_kernel<<<gi, 128>>>(q, out);
}

// round 7
// speedup vs baseline: 4.1785x; 1.0806x over previous
#include <cuda_runtime.h>
#include <cuda_bf16.h>
#include <cstdint>

#define CC 4
#define LL 1024
#define HH 8
#define DD 64
#define TT (CC*LL)
#define QSCALE 0.125f
#define EPSV 1e-6f
#define PTOT 2176   // 2080 unique (d<=e) pairs + 96 pad (17*128)
#define PREAL 2080

// Scratch (static __device__ — no allocation allowed)
__device__ float g_buf[CC*HH*LL];                 // [c][h][l] cumsum of log_g
__device__ float P_buf[(size_t)3*HH*PTOT*DD];     // [c'][h][p][v], chunks 0..2
__device__ float z_buf[3*HH*PTOT];                // per-chunk normalizer
__device__ float zs_buf[3*HH*PTOT];               // prefix normalizer
__device__ float row_buf[TT*HH];                  // intra row sums
__device__ short2 lut_de[PTOT];                   // (d,e) per pair
// pre-split bf16 operands, [h][t][d] layout (contiguous 128B rows per (c,h))
__device__ __nv_bfloat16 Qsh_g[(size_t)TT*HH*DD], Qsl_g[(size_t)TT*HH*DD];
__device__ __nv_bfloat16 Ksh_g[(size_t)TT*HH*DD], Ksl_g[(size_t)TT*HH*DD];
__device__ __nv_bfloat16 Vsh_g[(size_t)TT*HH*DD], Vsl_g[(size_t)TT*HH*DD];
// pre-split prefix states [c'][h][p][v]
__device__ __nv_bfloat16 Sh_g[(size_t)3*HH*PTOT*DD], Sl_g[(size_t)3*HH*PTOT*DD];

// ---------------------------------------------------------------------------
// mma.sync helpers (sm_80-level PTX; runs on Blackwell tensor pipe)
// ---------------------------------------------------------------------------
__device__ __forceinline__ uint32_t smem_u32(const void* p) {
    uint32_t a;
    asm("{ .reg .u64 t; cvta.to.shared.u64 t, %1; cvt.u32.u64 %0, t; }"
        : "=r"(a) : "l"(p));
    return a;
}
__device__ __forceinline__ void ldsm4(uint32_t* r, uint32_t a) {
    asm volatile("ldmatrix.sync.aligned.m8n8.x4.shared.b16 {%0,%1,%2,%3}, [%4];"
        : "=r"(r[0]), "=r"(r[1]), "=r"(r[2]), "=r"(r[3]) : "r"(a));
}
__device__ __forceinline__ void ldsm4t(uint32_t* r, uint32_t a) {
    asm volatile("ldmatrix.sync.aligned.m8n8.x4.trans.shared.b16 {%0,%1,%2,%3}, [%4];"
        : "=r"(r[0]), "=r"(r[1]), "=r"(r[2]), "=r"(r[3]) : "r"(a));
}
__device__ __forceinline__ void mma16816(float* d, const uint32_t* a, const uint32_t* b) {
    asm volatile("mma.sync.aligned.m16n8k16.row.col.f32.bf16.bf16.f32 "
        "{%0,%1,%2,%3}, {%4,%5,%6,%7}, {%8,%9}, {%0,%1,%2,%3};"
        : "+f"(d[0]), "+f"(d[1]), "+f"(d[2]), "+f"(d[3])
        : "r"(a[0]), "r"(a[1]), "r"(a[2]), "r"(a[3]), "r"(b[0]), "r"(b[1]));
}
__device__ __forceinline__ void mma16816s(float* d, const uint32_t* a,
                                          uint32_t b0, uint32_t b1) {
    asm volatile("mma.sync.aligned.m16n8k16.row.col.f32.bf16.bf16.f32 "
        "{%0,%1,%2,%3}, {%4,%5,%6,%7}, {%8,%9}, {%0,%1,%2,%3};"
        : "+f"(d[0]), "+f"(d[1]), "+f"(d[2]), "+f"(d[3])
        : "r"(a[0]), "r"(a[1]), "r"(a[2]), "r"(a[3]), "r"(b0), "r"(b1));
}
// fp32 -> (hi, lo) bf16 split store
__device__ __forceinline__ void split_st(__nv_bfloat16* hb, __nv_bfloat16* lb,
                                         int idx, float a) {
    __nv_bfloat16 hv = __float2bfloat16(a);
    hb[idx] = hv;
    lb[idx] = __float2bfloat16(a - __bfloat162float(hv));
}
// split two floats into packed bf16x2 hi and lo words (x low half, y high half)
__device__ __forceinline__ void split2(float x, float y, uint32_t& hi, uint32_t& lo) {
    __nv_bfloat16 xh = __float2bfloat16(x), yh = __float2bfloat16(y);
    __nv_bfloat16 xl = __float2bfloat16(x - __bfloat162float(xh));
    __nv_bfloat16 yl = __float2bfloat16(y - __bfloat162float(yh));
    hi = (uint32_t)*(uint16_t*)&xh | ((uint32_t)*(uint16_t*)&yh << 16);
    lo = (uint32_t)*(uint16_t*)&xl | ((uint32_t)*(uint16_t*)&yl << 16);
}

// ---------------------------------------------------------------------------
// K0a: pre-split Q*scale, K, V into global bf16 hi/lo, [h][t][d] layout.
// grid (TT/64, HH), 256 threads.
// ---------------------------------------------------------------------------
__global__ void split_kernel(const float* __restrict__ q,
                             const float* __restrict__ k,
                             const float* __restrict__ v) {
    const int t0 = blockIdx.x * 64, h = blockIdx.y;
    for (int idx = threadIdx.x; idx < 1024; idx += 256) {
        const int l = idx >> 4, d4 = (idx & 15) << 2;
        const int t = t0 + l;
        const size_t gi = ((size_t)t * HH + h) * DD + d4;
        const size_t oo = ((size_t)h * TT + t) * DD + d4;
        uint32_t a0, b0, a1, b1;
        const float4 qv = *(const float4*)&q[gi];
        split2(qv.x * QSCALE, qv.y * QSCALE, a0, b0);
        split2(qv.z * QSCALE, qv.w * QSCALE, a1, b1);
        *(uint2*)&Qsh_g[oo] = make_uint2(a0, a1);
        *(uint2*)&Qsl_g[oo] = make_uint2(b0, b1);
        const float4 kv = *(const float4*)&k[gi];
        split2(kv.x, kv.y, a0, b0);
        split2(kv.z, kv.w, a1, b1);
        *(uint2*)&Ksh_g[oo] = make_uint2(a0, a1);
        *(uint2*)&Ksl_g[oo] = make_uint2(b0, b1);
        const float4 vv = *(const float4*)&v[gi];
        split2(vv.x, vv.y, a0, b0);
        split2(vv.z, vv.w, a1, b1);
        *(uint2*)&Vsh_g[oo] = make_uint2(a0, a1);
        *(uint2*)&Vsl_g[oo] = make_uint2(b0, b1);
    }
}

// ---------------------------------------------------------------------------
// K0b: cumsum per (c,h) + pair-LUT build (last block)
// ---------------------------------------------------------------------------
__global__ void init_kernel(const float* __restrict__ lg) {
    if (blockIdx.x == CC * HH) {
        for (int p = threadIdx.x; p < PTOT; p += 256) {
            short d = 0, e = 0;
            if (p < PREAL) {
                int off = 0, dd = 0;
                while (off + (DD - dd) <= p) { off += DD - dd; dd++; }
                d = (short)dd; e = (short)(dd + (p - off));
            }
            lut_de[p] = make_short2(d, e);
        }
        return;
    }
    int c = blockIdx.x / HH, h = blockIdx.x % HH;
    int t = threadIdx.x;
    float vloc[4];
    float s = 0.f;
#pragma unroll
    for (int i = 0; i < 4; i++) {
        int l = t * 4 + i;
        s += lg[(c * LL + l) * HH + h];
        vloc[i] = s;
    }
    float tot = s;
#pragma unroll
    for (int off = 1; off < 32; off <<= 1) {
        float n = __shfl_up_sync(0xffffffffu, tot, off);
        if ((t & 31) >= off) tot += n;
    }
    __shared__ float wsum[8];
    __shared__ float woff[8];
    if ((t & 31) == 31) wsum[t >> 5] = tot;
    __syncthreads();
    if (t == 0) {
        float a = 0.f;
        for (int w = 0; w < 8; w++) { woff[w] = a; a += wsum[w]; }
    }
    __syncthreads();
    float ex = woff[t >> 5] + (tot - s);
#pragma unroll
    for (int i = 0; i < 4; i++)
        g_buf[(c * HH + h) * LL + t * 4 + i] = ex + vloc[i];
}

// ---------------------------------------------------------------------------
// K1: intra-chunk causal attention via bf16-split mma.sync.
// grid (16, H, C), 128 threads (4 warps). Staging = pure copies of presplit.
// ---------------------------------------------------------------------------
__global__ void __launch_bounds__(128) intra_tc_kernel(float* __restrict__ out) {
    __shared__ __align__(16) __nv_bfloat16 Qh[64 * 72], Ql[64 * 72];
    __shared__ __align__(16) __nv_bfloat16 Kh[32 * 72], Kl[32 * 72];
    __shared__ __align__(16) __nv_bfloat16 Vh[32 * 72], Vl[32 * 72];
    __shared__ float eqs[64], eks[32];
    const int tile = blockIdx.x, h = blockIdx.y, c = blockIdx.z;
    const int tid = threadIdx.x, lane = tid & 31, w = tid >> 5;
    const int l0 = tile * 64;

    {   // stage Q (copy presplit rows into stride-72 smem)
        const size_t qb = ((size_t)h * TT + c * LL + l0) * DD;
#pragma unroll
        for (int idx = tid; idx < 512; idx += 128) {
            const int l = idx >> 3, u = (idx & 7) * 8;
            *(uint4*)&Qh[l * 72 + u] = *(const uint4*)&Qsh_g[qb + l * 64 + u];
            *(uint4*)&Ql[l * 72 + u] = *(const uint4*)&Qsl_g[qb + l * 64 + u];
        }
    }
    if (tid < 64) eqs[tid] = __expf(g_buf[(c * HH + h) * LL + l0 + tid]);

    const int m0w = w * 16;
    const int r0 = m0w + (lane >> 2);
    const uint32_t QhB = smem_u32(Qh), QlB = smem_u32(Ql);
    const uint32_t KhB = smem_u32(Kh), KlB = smem_u32(Kl);
    const uint32_t VhB = smem_u32(Vh), VlB = smem_u32(Vl);
    const uint32_t aoffQ = ((m0w + (lane & 15)) * 72 + (lane >> 4) * 8) * 2;
    const uint32_t boff = ((lane & 15) * 72 + (lane >> 4) * 8) * 2;

    float oacc[8][4];
#pragma unroll
    for (int i = 0; i < 8; i++)
#pragma unroll
        for (int j = 0; j < 4; j++) oacc[i][j] = 0.f;
    float rs0 = 0.f, rs1 = 0.f;

    const int nst = 2 * (tile + 1);
    for (int st = 0; st < nst; st++) {
        __syncthreads();
        {   // stage K/V subtile (pure copy, batched loads for MLP)
            const size_t kb = ((size_t)h * TT + c * LL + st * 32) * DD;
#pragma unroll
            for (int idx = tid; idx < 256; idx += 128) {
                const int l = idx >> 3, u = (idx & 7) * 8;
                const int so = l * 72 + u;
                const size_t go = kb + l * 64 + u;
                const uint4 a = *(const uint4*)&Ksh_g[go];
                const uint4 b = *(const uint4*)&Ksl_g[go];
                const uint4 cc2 = *(const uint4*)&Vsh_g[go];
                const uint4 d = *(const uint4*)&Vsl_g[go];
                *(uint4*)&Kh[so] = a;
                *(uint4*)&Kl[so] = b;
                *(uint4*)&Vh[so] = cc2;
                *(uint4*)&Vl[so] = d;
            }
        }
        if (tid < 32) eks[tid] = __expf(-g_buf[(c * HH + h) * LL + st * 32 + tid]);
        __syncthreads();

        // GEMM1: scores[l][s] over d
        float sc[4][4];
#pragma unroll
        for (int i = 0; i < 4; i++)
#pragma unroll
            for (int j = 0; j < 4; j++) sc[i][j] = 0.f;
#pragma unroll
        for (int kd = 0; kd < 4; kd++) {
            uint32_t ah[4], al[4];
            ldsm4(ah, QhB + aoffQ + kd * 32);
            ldsm4(al, QlB + aoffQ + kd * 32);
#pragma unroll
            for (int ng = 0; ng < 2; ng++) {
                uint32_t kh4[4], kl4[4];
                const uint32_t rb = (uint32_t)(ng * 16 * 72 * 2) + boff + kd * 32;
                ldsm4(kh4, KhB + rb);
                ldsm4(kl4, KlB + rb);
                mma16816s(sc[ng * 2],     ah, kh4[0], kh4[2]);
                mma16816s(sc[ng * 2],     ah, kl4[0], kl4[2]);
                mma16816s(sc[ng * 2],     al, kh4[0], kh4[2]);
                mma16816s(sc[ng * 2 + 1], ah, kh4[1], kh4[3]);
                mma16816s(sc[ng * 2 + 1], ah, kl4[1], kl4[3]);
                mma16816s(sc[ng * 2 + 1], al, kh4[1], kh4[3]);
            }
        }

        // elementwise weight + causal mask + register repack to A-operand
        const float eq0 = eqs[r0], eq1 = eqs[r0 + 8];
        const int soff = st * 32 - l0;
        uint32_t wah[2][4], wal[2][4];
#pragma unroll
        for (int nt = 0; nt < 4; nt++) {
            const int sA = nt * 8 + 2 * (lane & 3);
            const float ekA = eks[sA], ekB = eks[sA + 1];
            float w00 = eq0 * ekA * sc[nt][0] * sc[nt][0];
            float w01 = eq0 * ekB * sc[nt][1] * sc[nt][1];
            float w10 = eq1 * ekA * sc[nt][2] * sc[nt][2];
            float w11 = eq1 * ekB * sc[nt][3] * sc[nt][3];
            if (soff >= 0) {
                if (r0 < soff + sA) w00 = 0.f;
                if (r0 < soff + sA + 1) w01 = 0.f;
                if (r0 + 8 < soff + sA) w10 = 0.f;
                if (r0 + 8 < soff + sA + 1) w11 = 0.f;
            }
            rs0 += w00 + w01;
            rs1 += w10 + w11;
            const int ks = nt >> 1, hf2 = (nt & 1) * 2;
            split2(w00, w01, wah[ks][hf2], wal[ks][hf2]);
            split2(w10, w11, wah[ks][hf2 + 1], wal[ks][hf2 + 1]);
        }

        // GEMM2: O += W * V
#pragma unroll
        for (int ks = 0; ks < 2; ks++) {
#pragma unroll
            for (int nv = 0; nv < 4; nv++) {
                uint32_t vh4[4], vl4[4];
                const uint32_t bo = boff + (uint32_t)(ks * 16 * 72 * 2) + nv * 32;
                ldsm4t(vh4, VhB + bo);
                ldsm4t(vl4, VlB + bo);
                mma16816s(oacc[nv * 2],     wah[ks], vh4[0], vh4[1]);
                mma16816s(oacc[nv * 2],     wah[ks], vl4[0], vl4[1]);
                mma16816s(oacc[nv * 2],     wal[ks], vh4[0], vh4[1]);
                mma16816s(oacc[nv * 2 + 1], wah[ks], vh4[2], vh4[3]);
                mma16816s(oacc[nv * 2 + 1], wah[ks], vl4[2], vl4[3]);
                mma16816s(oacc[nv * 2 + 1], wal[ks], vh4[2], vh4[3]);
            }
        }
    }

    rs0 += __shfl_xor_sync(0xffffffffu, rs0, 1);
    rs0 += __shfl_xor_sync(0xffffffffu, rs0, 2);
    rs1 += __shfl_xor_sync(0xffffffffu, rs1, 1);
    rs1 += __shfl_xor_sync(0xffffffffu, rs1, 2);
    const int t0 = c * LL + l0 + r0, t1 = t0 + 8;
    if ((lane & 3) == 0) {
        row_buf[t0 * HH + h] = rs0;
        row_buf[t1 * HH + h] = rs1;
    }
    float* O0 = &out[((size_t)t0 * HH + h) * DD];
    float* O1 = &out[((size_t)t1 * HH + h) * DD];
#pragma unroll
    for (int nt = 0; nt < 8; nt++) {
        const int c2 = nt * 8 + 2 * (lane & 3);
        *(float2*)&O0[c2] = make_float2(oacc[nt][0], oacc[nt][1]);
        *(float2*)&O1[c2] = make_float2(oacc[nt][2], oacc[nt][3]);
    }
}

// ---------------------------------------------------------------------------
// K2: pz via bf16-split mma.sync. grid (17, H, 3), 256 threads (8 warps).
// ---------------------------------------------------------------------------
__global__ void __launch_bounds__(256) pz_tc_kernel(const float* __restrict__ k) {
    __shared__ float Ks[32 * 67];                           // [l][d] fp32
    __shared__ __align__(16) __nv_bfloat16 Bh[32 * 72];     // V split hi [l][v]
    __shared__ __align__(16) __nv_bfloat16 Bl[32 * 72];
    __shared__ __align__(16) __nv_bfloat16 Ah[128 * 40];    // A split hi [p][l]
    __shared__ __align__(16) __nv_bfloat16 Al[128 * 40];
    __shared__ float wl[32];
    const int bt = blockIdx.x, h = blockIdx.y, c = blockIdx.z;
    const int tid = threadIdx.x, lane = tid & 31, w = tid >> 5;
    const int p0 = bt * 128;
    const short2 de = lut_de[p0 + (tid >> 1)];
    const float m0 = (p0 + (tid >> 1) >= PREAL) ? 0.f
                     : ((de.x == de.y) ? 1.f : 2.f);
    const int lh = (tid & 1) * 16;
    const int pr = tid >> 1;
    const float gend = g_buf[(c * HH + h) * LL + LL - 1];
    float zacc = 0.f;

    float acc[8][4];
#pragma unroll
    for (int i = 0; i < 8; i++)
#pragma unroll
        for (int j = 0; j < 4; j++) acc[i][j] = 0.f;

    const uint32_t AhB = smem_u32(Ah), AlB = smem_u32(Al);
    const uint32_t BhB = smem_u32(Bh), BlB = smem_u32(Bl);
    const int m0w = w * 16;
    const uint32_t aoff = ((m0w + (lane & 15)) * 40 + (lane >> 4) * 8) * 2;
    const uint32_t boff = ((lane & 15) * 72 + (lane >> 4) * 8) * 2;

    for (int lt = 0; lt < 32; lt++) {
        const int l0g = lt * 32;
        __syncthreads();
        {   // stage: K fp32 (for A build) + presplit V copy
            const size_t vb = ((size_t)h * TT + c * LL + l0g) * DD;
            for (int idx = tid; idx < 256; idx += 256) {
                const int l = idx >> 3, u = (idx & 7) * 8;
                const int so = l * 72 + u;
                const size_t go = vb + l * 64 + u;
                *(uint4*)&Bh[so] = *(const uint4*)&Vsh_g[go];
                *(uint4*)&Bl[so] = *(const uint4*)&Vsl_g[go];
            }
            for (int idx = tid; idx < 512; idx += 256) {
                const int l = idx >> 4, d4 = (idx & 15) << 2;
                const size_t gb = ((size_t)(c * LL + l0g + l) * HH + h) * DD + d4;
                const float4 kv = *(const float4*)&k[gb];
                Ks[l * 67 + d4 + 0] = kv.x;
                Ks[l * 67 + d4 + 1] = kv.y;
                Ks[l * 67 + d4 + 2] = kv.z;
                Ks[l * 67 + d4 + 3] = kv.w;
            }
        }
        if (tid < 32)
            wl[tid] = __expf(gend - g_buf[(c * HH + h) * LL + l0g + tid]);
        __syncthreads();
#pragma unroll
        for (int j = 0; j < 16; j++) {
            const int l = lh + j;
            const float a = m0 * wl[l] * Ks[l * 67 + de.x] * Ks[l * 67 + de.y];
            zacc += a;
            split_st(Ah, Al, pr * 40 + l, a);
        }
        __syncthreads();
#pragma unroll
        for (int ks = 0; ks < 2; ks++) {
            uint32_t ah[4], al[4];
            ldsm4(ah, AhB + aoff + ks * 32);
            ldsm4(al, AlB + aoff + ks * 32);
#pragma unroll
            for (int nt2 = 0; nt2 < 4; nt2++) {
                uint32_t bh[4], bl[4];
                const uint32_t bo = boff + ks * (16 * 72 * 2) + nt2 * 32;
                ldsm4t(bh, BhB + bo);
                ldsm4t(bl, BlB + bo);
                mma16816(acc[2 * nt2],     ah, bh);
                mma16816(acc[2 * nt2],     ah, bl);
                mma16816(acc[2 * nt2],     al, bh);
                mma16816(acc[2 * nt2 + 1], ah, bh + 2);
                mma16816(acc[2 * nt2 + 1], ah, bl + 2);
                mma16816(acc[2 * nt2 + 1], al, bh + 2);
            }
        }
    }

    const float zo = zacc + __shfl_xor_sync(0xffffffffu, zacc, 1);
    const size_t pb = (size_t)(c * HH + h) * PTOT + p0;
    if (!(tid & 1)) z_buf[pb + pr] = zo;

    const int r0 = m0w + (lane >> 2);
    float* P0 = &P_buf[(pb + r0) * 64];
    float* P1 = &P_buf[(pb + r0 + 8) * 64];
#pragma unroll
    for (int nt = 0; nt < 8; nt++) {
        const int c2 = nt * 8 + 2 * (lane & 3);
        *(float2*)&P0[c2] = make_float2(acc[nt][0], acc[nt][1]);
        *(float2*)&P1[c2] = make_float2(acc[nt][2], acc[nt][3]);
    }
}

// ---------------------------------------------------------------------------
// K2b: prefix-state combine; emits SPLIT bf16 prefix states directly.
// ---------------------------------------------------------------------------
__global__ void combineP_kernel() {
    const int perh = PTOT * 16;   // float4 per (c,h)
    int idx = blockIdx.x * 256 + threadIdx.x;
    if (idx >= HH * perh) return;
    int h = idx / perh, r = idx % perh;
    const float gt1 = __expf(g_buf[(1 * HH + h) * LL + LL - 1]);
    const float gt2 = __expf(g_buf[(2 * HH + h) * LL + LL - 1]);
    const float4* P = (const float4*)P_buf;
    const size_t o0 = (size_t)(0 * HH + h) * perh + r;
    const size_t o1 = (size_t)(1 * HH + h) * perh + r;
    const size_t o2 = (size_t)(2 * HH + h) * perh + r;
    const float4 p0 = P[o0], p1 = P[o1], p2 = P[o2];
    float4 s1 = p0;
    float4 s2 = make_float4(gt1 * s1.x + p1.x, gt1 * s1.y + p1.y,
                            gt1 * s1.z + p1.z, gt1 * s1.w + p1.w);
    float4 s3 = make_float4(gt2 * s2.x + p2.x, gt2 * s2.y + p2.y,
                            gt2 * s2.z + p2.z, gt2 * s2.w + p2.w);
    uint32_t a0, b0, a1, b1;
    split2(s1.x, s1.y, a0, b0); split2(s1.z, s1.w, a1, b1);
    *(uint2*)&Sh_g[o0 * 4] = make_uint2(a0, a1);
    *(uint2*)&Sl_g[o0 * 4] = make_uint2(b0, b1);
    split2(s2.x, s2.y, a0, b0); split2(s2.z, s2.w, a1, b1);
    *(uint2*)&Sh_g[o1 * 4] = make_uint2(a0, a1);
    *(uint2*)&Sl_g[o1 * 4] = make_uint2(b0, b1);
    split2(s3.x, s3.y, a0, b0); split2(s3.z, s3.w, a1, b1);
    *(uint2*)&Sh_g[o2 * 4] = make_uint2(a0, a1);
    *(uint2*)&Sl_g[o2 * 4] = make_uint2(b0, b1);
}

__global__ void combineZ_kernel() {
    int idx = blockIdx.x * 256 + threadIdx.x;
    if (idx >= HH * PTOT) return;
    int h = idx / PTOT, r = idx % PTOT;
    const float gt1 = __expf(g_buf[(1 * HH + h) * LL + LL - 1]);
    const float gt2 = __expf(g_buf[(2 * HH + h) * LL + LL - 1]);
    const float p0 = z_buf[(0 * HH + h) * PTOT + r];
    const float p1 = z_buf[(1 * HH + h) * PTOT + r];
    const float p2 = z_buf[(2 * HH + h) * PTOT + r];
    float s1 = p0;
    float s2 = gt1 * s1 + p1;
    float s3 = gt2 * s2 + p2;
    zs_buf[(0 * HH + h) * PTOT + r] = s1;
    zs_buf[(1 * HH + h) * PTOT + r] = s2;
    zs_buf[(2 * HH + h) * PTOT + r] = s3;
}

// ---------------------------------------------------------------------------
// K3: inter via bf16-split mma.sync + finalize. grid (16, H, C), 128 threads.
// ---------------------------------------------------------------------------
__global__ void __launch_bounds__(128) inter_tc_kernel(
    const float* __restrict__ q, float* __restrict__ out) {
    const int bx = blockIdx.x, h = blockIdx.y, c = blockIdx.z;
    const int tid = threadIdx.x, lane = tid & 31, w = tid >> 5;
    const int l0 = bx * 64;

    if (c == 0) {  // finalize only: divide intra numerator by row-sum
        for (int idx = tid; idx < 1024; idx += 128) {
            int l = idx >> 4, v4 = (idx & 15) << 2;
            const int t_ = l0 + l;
            const float inv = 1.f / fmaxf(row_buf[t_ * HH + h], EPSV);
            float4 ov = *(float4*)&out[((size_t)t_ * HH + h) * DD + v4];
            ov.x *= inv; ov.y *= inv; ov.z *= inv; ov.w *= inv;
            *(float4*)&out[((size_t)t_ * HH + h) * DD + v4] = ov;
        }
        return;
    }

    __shared__ float Qs[64 * 65];                           // [l][d] fp32 scaled
    __shared__ __align__(16) __nv_bfloat16 Ah[64 * 40];     // phiQ split [l][pp]
    __shared__ __align__(16) __nv_bfloat16 Al[64 * 40];
    __shared__ __align__(16) __nv_bfloat16 Bh[32 * 72];     // S split [pp][v]
    __shared__ __align__(16) __nv_bfloat16 Bl[32 * 72];
    __shared__ float zv[32];
    __shared__ short2 lutS[32];
    __shared__ float denp[128];
    __shared__ float denl[64];

    for (int idx = tid; idx < 1024; idx += 128) {
        int l = idx >> 4, d4 = (idx & 15) << 2;
        float4 qv = *(const float4*)&q[((size_t)(c * LL + l0 + l) * HH + h) * DD + d4];
        Qs[l * 65 + d4 + 0] = qv.x * QSCALE;
        Qs[l * 65 + d4 + 1] = qv.y * QSCALE;
        Qs[l * 65 + d4 + 2] = qv.z * QSCALE;
        Qs[l * 65 + d4 + 3] = qv.w * QSCALE;
    }
    const int lrow = tid >> 1, ph = (tid & 1) * 16;
    const float qdl = __expf(g_buf[(c * HH + h) * LL + l0 + lrow]);
    float dacc = 0.f;

    float acc[8][4];
#pragma unroll
    for (int i = 0; i < 8; i++)
#pragma unroll
        for (int j = 0; j < 4; j++) acc[i][j] = 0.f;

    const size_t Sbase = (size_t)((c - 1) * HH + h) * PTOT * DD;
    const float* zp = &zs_buf[((c - 1) * HH + h) * PTOT];
    const uint32_t AhB = smem_u32(Ah), AlB = smem_u32(Al);
    const uint32_t BhB = smem_u32(Bh), BlB = smem_u32(Bl);
    const int m0w = w * 16;
    const uint32_t aoff = ((m0w + (lane & 15)) * 40 + (lane >> 4) * 8) * 2;
    const uint32_t boff = ((lane & 15) * 72 + (lane >> 4) * 8) * 2;

    for (int pt = 0; pt < PTOT / 32; pt++) {
        const int p0 = pt * 32;
        __syncthreads();
        {   // stage S tile: pure copy of presplit
            const size_t sb2 = Sbase + (size_t)p0 * 64;
#pragma unroll
            for (int idx = tid; idx < 256; idx += 128) {
                const int pp = idx >> 3, u = (idx & 7) * 8;
                const int so = pp * 72 + u;
                const size_t go = sb2 + pp * 64 + u;
                *(uint4*)&Bh[so] = *(const uint4*)&Sh_g[go];
                *(uint4*)&Bl[so] = *(const uint4*)&Sl_g[go];
            }
        }
        if (tid < 32) {
            zv[tid] = zp[p0 + tid];
            lutS[tid] = lut_de[p0 + tid];
        }
        __syncthreads();
#pragma unroll
        for (int j = 0; j < 16; j++) {
            const int pp = ph + j;
            const short2 de = lutS[pp];
            const float a = qdl * Qs[lrow * 65 + de.x] * Qs[lrow * 65 + de.y];
            dacc += a * zv[pp];
            split_st(Ah, Al, lrow * 40 + pp, a);
        }
        __syncthreads();
#pragma unroll
        for (int ks = 0; ks < 2; ks++) {
            uint32_t ah[4], al[4];
            ldsm4(ah, AhB + aoff + ks * 32);
            ldsm4(al, AlB + aoff + ks * 32);
#pragma unroll
            for (int nt2 = 0; nt2 < 4; nt2++) {
                uint32_t bh[4], bl[4];
                const uint32_t bo = boff + ks * (16 * 72 * 2) + nt2 * 32;
                ldsm4t(bh, BhB + bo);
                ldsm4t(bl, BlB + bo);
                mma16816(acc[2 * nt2],     ah, bh);
                mma16816(acc[2 * nt2],     ah, bl);
                mma16816(acc[2 * nt2],     al, bh);
                mma16816(acc[2 * nt2 + 1], ah, bh + 2);
                mma16816(acc[2 * nt2 + 1], ah, bl + 2);
                mma16816(acc[2 * nt2 + 1], al, bh + 2);
            }
        }
    }

    denp[tid] = dacc;
    __syncthreads();
    if (tid < 64) denl[tid] = denp[2 * tid] + denp[2 * tid + 1];
    __syncthreads();

    const int r0 = m0w + (lane >> 2);
    const int t0 = c * LL + l0 + r0, t1 = t0 + 8;
    const float inv0 = 1.f / fmaxf(row_buf[t0 * HH + h] + denl[r0], EPSV);
    const float inv1 = 1.f / fmaxf(row_buf[t1 * HH + h] + denl[r0 + 8], EPSV);
    float* O0 = &out[((size_t)t0 * HH + h) * DD];
    float* O1 = &out[((size_t)t1 * HH + h) * DD];
#pragma unroll
    for (int nt = 0; nt < 8; nt++) {
        const int c2 = nt * 8 + 2 * (lane & 3);
        float2 o0 = *(float2*)&O0[c2];
        o0.x = (o0.x + acc[nt][0]) * inv0;
        o0.y = (o0.y + acc[nt][1]) * inv0;
        *(float2*)&O0[c2] = o0;
        float2 o1 = *(float2*)&O1[c2];
        o1.x = (o1.x + acc[nt][2]) * inv1;
        o1.y = (o1.y + acc[nt][3]) * inv1;
        *(float2*)&O1[c2] = o1;
    }
}

extern "C" void kernel_launch(void* const* d_in, const int* in_sizes, int n_in,
                              void* d_out, int out_size) {
    const float* q = (const float*)d_in[0];
    const float* k = (const float*)d_in[1];
    const float* v = (const float*)d_in[2];
    const float* lg = (const float*)d_in[3];
    float* out = (float*)d_out;

    init_kernel<<<CC * HH + 1, 256>>>(lg);

    dim3 gs(TT / 64, HH);
    split_kernel<<<gs, 256>>>(q, k, v);

    dim3 gt(16, HH, CC);
    intra_tc_kernel<<<gt, 128>>>(out);

    dim3 gp(PTOT / 128, HH, CC - 1);
    pz_tc_kernel<<<gp, 256>>>(k);

    combineP_kernel<<<(HH * PTOT * 16 + 255) / 256, 256>>>();
    combineZ_kernel<<<(HH * PTOT + 255) / 256, 256>>>();

    dim3 gi(16, HH, CC);
    inter_tc_kernel<<<gi, 128>>>(q, out);
}